// round 2
// baseline (speedup 1.0000x reference)
#include <cuda_runtime.h>

// Fused window cross-attention, one CTA per window (fp32 baseline).
// Phases per window:
//   0: load kv rows -> smem
//   1: kv projection -> K,V in smem
//   2: per 32-row q chunk: load q, q-proj, per-row attention (softmax+bias), out-proj
namespace {
constexpr int NKEY = 49;
constexpr int QN_  = 196;
constexpr int DIM_ = 384;
constexpr int NH_  = 12;
constexpr int HD_  = 32;
constexpr int CQ_  = 192;   // q input dim and output dim
constexpr float SCALE_ = 0.17677669529663687f;  // 32^-0.5

constexpr int SKV   = 385;  // padded stride (385 % 32 == 1 -> conflict-free)
constexpr int NT    = 256;
constexpr int CHUNK = 32;

// smem layout in floats
constexpr int OFF_K   = 0;
constexpr int OFF_V   = NKEY * SKV;
constexpr int OFF_R1  = 2 * NKEY * SKV;          // scratch region, 49*384 floats
constexpr int OFF_QIN = OFF_R1;                  // chunk q input: 32*192
constexpr int OFF_QP  = OFF_R1 + CHUNK * CQ_;    // chunk qp / o rows: 32*384
constexpr int OFF_P   = OFF_R1 + NKEY * DIM_;    // per-warp softmax probs: 8*64
constexpr int SMEM_FLOATS = OFF_P + 8 * 64;      // 57,058 floats = 228,232 B
}

__device__ __forceinline__ int rel_bias_idx(int qr, int key) {
    // query qr in 0..195 on the 14x14 grid; key in 0..48 maps to grid pos 4*key
    int qi = qr / 14, qj = qr - qi * 14;
    int kp = key * 4;
    int ki = kp / 14, kj = kp - ki * 14;
    int dh = (qi >> 1) - (ki >> 1) + 6;
    int dw = (qj >> 1) - (kj >> 1) + 6;
    return dh * 13 + dw;
}

__global__ __launch_bounds__(NT, 1)
void wca_kernel(const float* __restrict__ kv, const float* __restrict__ q,
                const float* __restrict__ w_kv, const float* __restrict__ b_kv,
                const float* __restrict__ w_q, const float* __restrict__ b_q,
                const float* __restrict__ bias_table,
                const float* __restrict__ w_proj, const float* __restrict__ b_proj,
                float* __restrict__ out)
{
    extern __shared__ float smf[];
    float* s_k   = smf + OFF_K;
    float* s_v   = smf + OFF_V;
    float* s_r1  = smf + OFF_R1;
    float* s_qin = smf + OFF_QIN;
    float* s_qp  = smf + OFF_QP;
    float* s_p   = smf + OFF_P;

    const int b   = blockIdx.x;
    const int tid = threadIdx.x;

    // ---- phase 0: load kv rows (49x384) ----
    const float* kvb = kv + (size_t)b * (NKEY * DIM_);
    for (int i = tid; i < NKEY * DIM_; i += NT) s_r1[i] = kvb[i];
    __syncthreads();

    // ---- phase 1: kv projection -> K (cols 0..383), V (cols 384..767) ----
    {
        const int c0 = tid, c1 = tid + 256, c2 = tid + 512;
        const float bb0 = b_kv[c0], bb1 = b_kv[c1], bb2 = b_kv[c2];
        for (int g = 0; g < 4; ++g) {
            const int n0 = g * 16;
            const int cnt = (NKEY - n0) < 16 ? (NKEY - n0) : 16;
            if (cnt == 16) {
                float a0[16], a1[16], a2[16];
                #pragma unroll
                for (int r = 0; r < 16; ++r) { a0[r] = bb0; a1[r] = bb1; a2[r] = bb2; }
                #pragma unroll 2
                for (int k = 0; k < DIM_; ++k) {
                    const float w0 = w_kv[k * 768 + c0];
                    const float w1 = w_kv[k * 768 + c1];
                    const float w2 = w_kv[k * 768 + c2];
                    const float* xr = s_r1 + n0 * DIM_ + k;
                    #pragma unroll
                    for (int r = 0; r < 16; ++r) {
                        const float x = xr[r * DIM_];
                        a0[r] = fmaf(x, w0, a0[r]);
                        a1[r] = fmaf(x, w1, a1[r]);
                        a2[r] = fmaf(x, w2, a2[r]);
                    }
                }
                #pragma unroll
                for (int r = 0; r < 16; ++r) {
                    const int n = n0 + r;
                    s_k[n * SKV + c0] = a0[r];
                    if (c1 < DIM_) s_k[n * SKV + c1] = a1[r];
                    else           s_v[n * SKV + (c1 - DIM_)] = a1[r];
                    s_v[n * SKV + (c2 - DIM_)] = a2[r];
                }
            } else {
                for (int r = 0; r < cnt; ++r) {
                    const int n = n0 + r;
                    float a0 = bb0, a1 = bb1, a2 = bb2;
                    const float* xr = s_r1 + n * DIM_;
                    for (int k = 0; k < DIM_; ++k) {
                        const float x = xr[k];
                        a0 = fmaf(x, w_kv[k * 768 + c0], a0);
                        a1 = fmaf(x, w_kv[k * 768 + c1], a1);
                        a2 = fmaf(x, w_kv[k * 768 + c2], a2);
                    }
                    s_k[n * SKV + c0] = a0;
                    if (c1 < DIM_) s_k[n * SKV + c1] = a1;
                    else           s_v[n * SKV + (c1 - DIM_)] = a1;
                    s_v[n * SKV + (c2 - DIM_)] = a2;
                }
            }
        }
    }
    __syncthreads();

    // ---- phase 2: q chunks ----
    const int wi = tid >> 5, lane = tid & 31;
    for (int q0 = 0; q0 < QN_; q0 += CHUNK) {
        const int nr = (QN_ - q0) < CHUNK ? (QN_ - q0) : CHUNK;

        // 2a: load q chunk
        const float* qb = q + (size_t)b * (QN_ * CQ_) + (size_t)q0 * CQ_;
        for (int i = tid; i < nr * CQ_; i += NT) s_qin[i] = qb[i];
        __syncthreads();

        // 2b: q projection -> s_qp[r][0..383]
        if (tid < 192) {
            const int c0 = tid, c1 = tid + 192;
            const float bq0 = b_q[c0], bq1 = b_q[c1];
            for (int g = 0; g < 2; ++g) {
                const int r0 = g * 16;
                const int cnt = min(16, nr - r0);
                if (cnt <= 0) break;
                if (cnt == 16) {
                    float a0[16], a1[16];
                    #pragma unroll
                    for (int r = 0; r < 16; ++r) { a0[r] = bq0; a1[r] = bq1; }
                    #pragma unroll 2
                    for (int k = 0; k < CQ_; ++k) {
                        const float w0 = w_q[k * DIM_ + c0];
                        const float w1 = w_q[k * DIM_ + c1];
                        const float* xr = s_qin + r0 * CQ_ + k;
                        #pragma unroll
                        for (int r = 0; r < 16; ++r) {
                            const float x = xr[r * CQ_];
                            a0[r] = fmaf(x, w0, a0[r]);
                            a1[r] = fmaf(x, w1, a1[r]);
                        }
                    }
                    #pragma unroll
                    for (int r = 0; r < 16; ++r) {
                        s_qp[(r0 + r) * DIM_ + c0] = a0[r];
                        s_qp[(r0 + r) * DIM_ + c1] = a1[r];
                    }
                } else {
                    for (int r = 0; r < cnt; ++r) {
                        float a0 = bq0, a1 = bq1;
                        const float* xr = s_qin + (r0 + r) * CQ_;
                        for (int k = 0; k < CQ_; ++k) {
                            const float x = xr[k];
                            a0 = fmaf(x, w_q[k * DIM_ + c0], a0);
                            a1 = fmaf(x, w_q[k * DIM_ + c1], a1);
                        }
                        s_qp[(r0 + r) * DIM_ + c0] = a0;
                        s_qp[(r0 + r) * DIM_ + c1] = a1;
                    }
                }
            }
        }
        __syncthreads();

        // 2c: attention, warp per q row; o overwrites qp row in place per head
        {
            const int key2  = 32 + lane;
            const bool v2   = key2 < NKEY;          // lanes 0..16 hold a 2nd key
            const int key2c = v2 ? key2 : 0;
            for (int r = wi; r < nr; r += 8) {
                const int qr  = q0 + r;
                const int bi1 = rel_bias_idx(qr, lane) * NH_;
                const int bi2 = rel_bias_idx(qr, key2c) * NH_;
                float* qprow = s_qp + r * DIM_;
                for (int h = 0; h < NH_; ++h) {
                    const int base = h * HD_;
                    const float* kp1 = s_k + lane  * SKV + base;
                    const float* kp2 = s_k + key2c * SKV + base;
                    float l1 = 0.f, l2 = 0.f;
                    #pragma unroll
                    for (int d = 0; d < HD_; ++d) {
                        const float qv = qprow[base + d];
                        l1 = fmaf(qv, kp1[d], l1);
                        l2 = fmaf(qv, kp2[d], l2);
                    }
                    l1 = l1 * SCALE_ + bias_table[bi1 + h];
                    l2 = v2 ? (l2 * SCALE_ + bias_table[bi2 + h]) : -1e30f;
                    float m = fmaxf(l1, l2);
                    #pragma unroll
                    for (int o = 16; o; o >>= 1)
                        m = fmaxf(m, __shfl_xor_sync(0xffffffffu, m, o));
                    const float p1 = __expf(l1 - m);
                    const float p2 = v2 ? __expf(l2 - m) : 0.f;
                    float ssum = p1 + p2;
                    #pragma unroll
                    for (int o = 16; o; o >>= 1)
                        ssum += __shfl_xor_sync(0xffffffffu, ssum, o);
                    const float inv = 1.0f / ssum;
                    s_p[wi * 64 + lane]      = p1 * inv;
                    s_p[wi * 64 + 32 + lane] = p2 * inv;
                    __syncwarp();
                    // AV: lane == head dim d
                    float oacc = 0.f;
                    const float* vp = s_v + base + lane;
                    const float* pp = s_p + wi * 64;
                    #pragma unroll
                    for (int k = 0; k < NKEY; ++k)
                        oacc = fmaf(pp[k], vp[k * SKV], oacc);
                    __syncwarp();
                    qprow[base + lane] = oacc;   // overwrite qp head-h slot with o
                }
            }
        }
        __syncthreads();

        // 2d: output projection o(384) @ w_proj(384x192) + b_proj -> gmem
        if (tid < 192) {
            const int j = tid;
            const float bp = b_proj[j];
            for (int g = 0; g < 2; ++g) {
                const int r0 = g * 16;
                const int cnt = min(16, nr - r0);
                if (cnt <= 0) break;
                if (cnt == 16) {
                    float acc[16];
                    #pragma unroll
                    for (int r = 0; r < 16; ++r) acc[r] = bp;
                    #pragma unroll 2
                    for (int c = 0; c < DIM_; ++c) {
                        const float w = w_proj[c * CQ_ + j];
                        const float* xr = s_qp + r0 * DIM_ + c;
                        #pragma unroll
                        for (int r = 0; r < 16; ++r)
                            acc[r] = fmaf(xr[r * DIM_], w, acc[r]);
                    }
                    float* ob = out + (size_t)b * (QN_ * CQ_) + (size_t)(q0 + r0) * CQ_ + j;
                    #pragma unroll
                    for (int r = 0; r < 16; ++r) ob[r * CQ_] = acc[r];
                } else {
                    for (int r = 0; r < cnt; ++r) {
                        float acc = bp;
                        const float* xr = s_qp + (r0 + r) * DIM_;
                        for (int c = 0; c < DIM_; ++c)
                            acc = fmaf(xr[c], w_proj[c * CQ_ + j], acc);
                        out[(size_t)b * (QN_ * CQ_) + (size_t)(q0 + r0 + r) * CQ_ + j] = acc;
                    }
                }
            }
        }
        __syncthreads();
    }
}

extern "C" void kernel_launch(void* const* d_in, const int* in_sizes, int n_in,
                              void* d_out, int out_size) {
    const float* kv         = (const float*)d_in[0];
    const float* q          = (const float*)d_in[1];
    const float* w_kv       = (const float*)d_in[2];
    const float* b_kv       = (const float*)d_in[3];
    const float* w_q        = (const float*)d_in[4];
    const float* b_q        = (const float*)d_in[5];
    const float* bias_table = (const float*)d_in[6];
    const float* w_proj     = (const float*)d_in[7];
    const float* b_proj     = (const float*)d_in[8];
    float* out = (float*)d_out;

    const int B = in_sizes[0] / (NKEY * DIM_);   // 2048
    const size_t smem = (size_t)SMEM_FLOATS * sizeof(float);  // 228,232 B
    cudaFuncSetAttribute(wca_kernel, cudaFuncAttributeMaxDynamicSharedMemorySize, (int)smem);
    wca_kernel<<<B, NT, smem>>>(kv, q, w_kv, b_kv, w_q, b_q, bias_table,
                                w_proj, b_proj, out);
}

// round 3
// speedup vs baseline: 2.0194x; 2.0194x over previous
#include <cuda_runtime.h>
#include <mma.h>

using namespace nvcuda;

namespace {
constexpr int NKEY = 49;
constexpr int QN_  = 196;
constexpr int DIM_ = 384;
constexpr int NH_  = 12;
constexpr int HD_  = 32;
constexpr int CQ_  = 192;
constexpr float SCALE_ = 0.17677669529663687f;  // 32^-0.5

constexpr int SKV    = 388;   // K/V row stride (mult of 4 for wmma ldm)
constexpr int NT     = 384;   // 12 warps
constexpr int NW     = 12;
constexpr int CHUNK  = 16;    // q rows per chunk
constexpr int STG_LD = 52;    // softmax staging stride (cols 0-47 S, 48 p48, 49 inv)

// smem layout (floats)
constexpr int OFF_K   = 0;
constexpr int OFF_V   = OFF_K + NKEY * SKV;                 // 19012
constexpr int OFF_SCR = OFF_V + NKEY * SKV;                 // 38024
// phase1: s_x = SCR, 49*384 = 18816
// chunks: s_qin = SCR (16*192=3072); s_qp = SCR+3072 (16*384=6144);
//         s_stg = SCR+9216 (12*16*52 = 9984)  -> chunk scratch = 19200
constexpr int SCR_SIZE = 19200;
constexpr int OFF_RIDX = OFF_SCR + SCR_SIZE;                // 57224 (784 ints)
constexpr int SMEM_FLOATS = OFF_RIDX + CHUNK * NKEY;        // 58008 -> 232032 B

using FragA  = wmma::fragment<wmma::matrix_a, 16, 16, 8, wmma::precision::tf32, wmma::row_major>;
using FragBR = wmma::fragment<wmma::matrix_b, 16, 16, 8, wmma::precision::tf32, wmma::row_major>;
using FragBC = wmma::fragment<wmma::matrix_b, 16, 16, 8, wmma::precision::tf32, wmma::col_major>;
using FragC  = wmma::fragment<wmma::accumulator, 16, 16, 8, float>;
}

template <typename F>
__device__ __forceinline__ void cvt_tf32(F& f) {
#pragma unroll
    for (int i = 0; i < f.num_elements; ++i) f.x[i] = wmma::__float_to_tf32(f.x[i]);
}

__device__ __forceinline__ int rel_bias_idx(int qr, int key) {
    int qi = qr / 14, qj = qr - qi * 14;
    int kp = key * 4;
    int ki = kp / 14, kj = kp - ki * 14;
    int dh = (qi >> 1) - (ki >> 1) + 6;
    int dw = (qj >> 1) - (kj >> 1) + 6;
    return dh * 13 + dw;
}

__global__ __launch_bounds__(NT, 1)
void wca_kernel(const float* __restrict__ kv, const float* __restrict__ q,
                const float* __restrict__ w_kv, const float* __restrict__ b_kv,
                const float* __restrict__ w_q, const float* __restrict__ b_q,
                const float* __restrict__ bias_table,
                const float* __restrict__ w_proj, const float* __restrict__ b_proj,
                float* __restrict__ out)
{
    extern __shared__ float sm[];
    float* s_k   = sm + OFF_K;
    float* s_v   = sm + OFF_V;
    float* s_x   = sm + OFF_SCR;                       // phase 1 only
    float* s_qin = sm + OFF_SCR;                       // chunk phase
    float* s_qp  = sm + OFF_SCR + CHUNK * CQ_;
    float* s_stg = sm + OFF_SCR + CHUNK * CQ_ + CHUNK * DIM_;
    int*   s_ridx = (int*)(sm + OFF_RIDX);

    const int b    = blockIdx.x;
    const int tid  = threadIdx.x;
    const int wid  = tid >> 5;
    const int lane = tid & 31;

    // ---------- phase 0: load kv-input X (49x384) ----------
    {
        const float4* src = (const float4*)(kv + (size_t)b * NKEY * DIM_);
        for (int i = tid; i < NKEY * DIM_ / 4; i += NT) ((float4*)s_x)[i] = src[i];
    }
    __syncthreads();

    // ---------- phase 1: kv projection (rows 0..47 via wmma) ----------
    // C[49x768] = X[49x384] @ W_kv[384x768]; 24 jobs of (16 rows x 96 cols)
    for (int j = wid; j < 24; j += NW) {
        const int m = j >> 3;          // 0..2 -> rows m*16..m*16+15
        const int col0 = (j & 7) * 96; // 0..672
        FragC c[6];
#pragma unroll
        for (int t = 0; t < 6; ++t) wmma::fill_fragment(c[t], 0.0f);
        for (int ks = 0; ks < 48; ++ks) {
            FragA a;
            wmma::load_matrix_sync(a, s_x + m * 16 * DIM_ + ks * 8, DIM_);
            cvt_tf32(a);
#pragma unroll
            for (int t = 0; t < 6; ++t) {
                FragBR bf;
                wmma::load_matrix_sync(bf, w_kv + ks * 8 * 768 + col0 + t * 16, 768);
                cvt_tf32(bf);
                wmma::mma_sync(c[t], a, bf, c[t]);
            }
        }
#pragma unroll
        for (int t = 0; t < 6; ++t) {
            const int col = col0 + t * 16;
            float* dst = (col < DIM_) ? (s_k + m * 16 * SKV + col)
                                      : (s_v + m * 16 * SKV + (col - DIM_));
            wmma::store_matrix_sync(dst, c[t], SKV, wmma::mem_row_major);
        }
    }
    __syncthreads();

    // bias add for rows 0..47, plus scalar row 48 (GEMM + bias)
    for (int i = tid; i < 48 * 768; i += NT) {
        const int r = i / 768, cc = i - r * 768;
        if (cc < DIM_) s_k[r * SKV + cc] += b_kv[cc];
        else           s_v[r * SKV + cc - DIM_] += b_kv[cc];
    }
    {
        const float* x48 = s_x + 48 * DIM_;
        for (int cc = tid; cc < 768; cc += NT) {
            float acc = b_kv[cc];
#pragma unroll 4
            for (int k = 0; k < DIM_; ++k) acc = fmaf(x48[k], w_kv[k * 768 + cc], acc);
            if (cc < DIM_) s_k[48 * SKV + cc] = acc;
            else           s_v[48 * SKV + cc - DIM_] = acc;
        }
    }
    __syncthreads();

    // ---------- phase 2: q chunks of 16 rows ----------
    for (int q0 = 0; q0 < QN_; q0 += CHUNK) {
        const int nr = min(CHUNK, QN_ - q0);

        // 2a: load q chunk (zero-pad rows >= nr) + rel-idx table
        {
            const float4* src = (const float4*)(q + (size_t)b * QN_ * CQ_ + (size_t)q0 * CQ_);
            const int lim = nr * CQ_ / 4;
            for (int i = tid; i < CHUNK * CQ_ / 4; i += NT) {
                float4 v = make_float4(0.f, 0.f, 0.f, 0.f);
                if (i < lim) v = src[i];
                ((float4*)s_qin)[i] = v;
            }
            for (int i = tid; i < CHUNK * NKEY; i += NT) {
                const int r = i / NKEY, key = i - r * NKEY;
                const int qr = min(q0 + r, QN_ - 1);
                s_ridx[i] = rel_bias_idx(qr, key) * NH_;
            }
        }
        __syncthreads();

        // 2b: q projection: C[16x384] = Xq[16x192] @ W_q[192x384]; warp -> 32 cols
        {
            const int col0 = wid * 32;
            FragC c[2];
            wmma::fill_fragment(c[0], 0.0f);
            wmma::fill_fragment(c[1], 0.0f);
            for (int ks = 0; ks < 24; ++ks) {
                FragA a;
                wmma::load_matrix_sync(a, s_qin + ks * 8, CQ_);
                cvt_tf32(a);
#pragma unroll
                for (int t = 0; t < 2; ++t) {
                    FragBR bf;
                    wmma::load_matrix_sync(bf, w_q + ks * 8 * DIM_ + col0 + t * 16, DIM_);
                    cvt_tf32(bf);
                    wmma::mma_sync(c[t], a, bf, c[t]);
                }
            }
            wmma::store_matrix_sync(s_qp + col0,      c[0], DIM_, wmma::mem_row_major);
            wmma::store_matrix_sync(s_qp + col0 + 16, c[1], DIM_, wmma::mem_row_major);
        }
        __syncthreads();
        for (int i = tid; i < CHUNK * DIM_; i += NT) s_qp[i] += b_q[i % DIM_];
        __syncthreads();

        // 2c: attention — warp wid handles head wid
        {
            const int h = wid;
            const int base = h * HD_;
            float* stg = s_stg + wid * (CHUNK * STG_LD);

            // S = Q_h @ K_h^T (keys 0..47 via wmma)
            FragC s[3];
#pragma unroll
            for (int t = 0; t < 3; ++t) wmma::fill_fragment(s[t], 0.0f);
#pragma unroll
            for (int ks = 0; ks < 4; ++ks) {
                FragA a;
                wmma::load_matrix_sync(a, s_qp + base + ks * 8, DIM_);
                cvt_tf32(a);
#pragma unroll
                for (int t = 0; t < 3; ++t) {
                    FragBC bk;
                    wmma::load_matrix_sync(bk, s_k + (t * 16) * SKV + base + ks * 8, SKV);
                    cvt_tf32(bk);
                    wmma::mma_sync(s[t], a, bk, s[t]);
                }
            }
#pragma unroll
            for (int t = 0; t < 3; ++t)
                wmma::store_matrix_sync(stg + t * 16, s[t], STG_LD, wmma::mem_row_major);

            // scalar: key 48 logits
            if (lane < CHUNK) {
                float acc = 0.f;
                const float* qrow = s_qp + lane * DIM_ + base;
                const float* k48  = s_k + 48 * SKV + base;
#pragma unroll
                for (int d = 0; d < HD_; ++d) acc = fmaf(qrow[d], k48[d], acc);
                stg[lane * STG_LD + 48] = acc;
            }
            __syncwarp();

            // softmax (2 lanes per row); leaves unnormalized p in cols 0..48, 1/sum in col 49
            {
                const int r = lane >> 1, par = lane & 1;
                float* row = stg + r * STG_LD;
                const int* rix = s_ridx + r * NKEY;
                float mx = -1e30f;
                for (int c = par; c < NKEY; c += 2) {
                    const float vv = row[c] * SCALE_ + bias_table[rix[c] + h];
                    row[c] = vv;
                    mx = fmaxf(mx, vv);
                }
                mx = fmaxf(mx, __shfl_xor_sync(0xffffffffu, mx, 1));
                float ssum = 0.f;
                for (int c = par; c < NKEY; c += 2) {
                    const float p = __expf(row[c] - mx);
                    row[c] = p;
                    ssum += p;
                }
                ssum += __shfl_xor_sync(0xffffffffu, ssum, 1);
                if (par == 0) row[49] = 1.0f / ssum;
            }
            __syncwarp();

            // O = P @ V (keys 0..47 via wmma), stored into s_qp in place
            FragC o[2];
            wmma::fill_fragment(o[0], 0.0f);
            wmma::fill_fragment(o[1], 0.0f);
#pragma unroll
            for (int ks = 0; ks < 6; ++ks) {
                FragA a;
                wmma::load_matrix_sync(a, stg + ks * 8, STG_LD);
                cvt_tf32(a);
#pragma unroll
                for (int t = 0; t < 2; ++t) {
                    FragBR bv;
                    wmma::load_matrix_sync(bv, s_v + ks * 8 * SKV + base + t * 16, SKV);
                    cvt_tf32(bv);
                    wmma::mma_sync(o[t], a, bv, o[t]);
                }
            }
            wmma::store_matrix_sync(s_qp + base,      o[0], DIM_, wmma::mem_row_major);
            wmma::store_matrix_sync(s_qp + base + 16, o[1], DIM_, wmma::mem_row_major);
            __syncwarp();

            // epilogue: add key-48 contribution, normalize
            {
                const int r = lane >> 1, d0 = (lane & 1) * 16;
                const float p48 = stg[r * STG_LD + 48];
                const float inv = stg[r * STG_LD + 49];
                float* orow = s_qp + r * DIM_ + base + d0;
                const float* v48 = s_v + 48 * SKV + base + d0;
#pragma unroll
                for (int d = 0; d < 16; ++d) orow[d] = (orow[d] + p48 * v48[d]) * inv;
            }
        }
        __syncthreads();

        // 2d: out projection: C[16x192] = O[16x384] @ W_proj[384x192]; warp -> 16 cols
        {
            const int col0 = wid * 16;
            FragC c;
            wmma::fill_fragment(c, 0.0f);
            for (int ks = 0; ks < 48; ++ks) {
                FragA a;
                wmma::load_matrix_sync(a, s_qp + ks * 8, DIM_);
                cvt_tf32(a);
                FragBR bw;
                wmma::load_matrix_sync(bw, w_proj + ks * 8 * CQ_ + col0, CQ_);
                cvt_tf32(bw);
                wmma::mma_sync(c, a, bw, c);
            }
            wmma::store_matrix_sync(s_qin + col0, c, CQ_, wmma::mem_row_major);  // s_qin = out staging
        }
        __syncthreads();

        // copy to gmem with bias (rows < nr only)
        {
            float4* ob = (float4*)(out + (size_t)b * QN_ * CQ_ + (size_t)q0 * CQ_);
            for (int i = tid; i < nr * CQ_ / 4; i += NT) {
                float4 v = ((float4*)s_qin)[i];
                const int j4 = (i * 4) % CQ_;
                const float4 bp = *(const float4*)(b_proj + j4);
                v.x += bp.x; v.y += bp.y; v.z += bp.z; v.w += bp.w;
                ob[i] = v;
            }
        }
        __syncthreads();
    }
}

extern "C" void kernel_launch(void* const* d_in, const int* in_sizes, int n_in,
                              void* d_out, int out_size) {
    const float* kv         = (const float*)d_in[0];
    const float* q          = (const float*)d_in[1];
    const float* w_kv       = (const float*)d_in[2];
    const float* b_kv       = (const float*)d_in[3];
    const float* w_q        = (const float*)d_in[4];
    const float* b_q        = (const float*)d_in[5];
    const float* bias_table = (const float*)d_in[6];
    const float* w_proj     = (const float*)d_in[7];
    const float* b_proj     = (const float*)d_in[8];
    float* out = (float*)d_out;

    const int B = in_sizes[0] / (NKEY * DIM_);              // 2048
    const size_t smem = (size_t)SMEM_FLOATS * sizeof(float); // 232,032 B
    cudaFuncSetAttribute(wca_kernel, cudaFuncAttributeMaxDynamicSharedMemorySize, (int)smem);
    wca_kernel<<<B, NT, smem>>>(kv, q, w_kv, b_kv, w_q, b_q, bias_table,
                                w_proj, b_proj, out);
}

// round 4
// speedup vs baseline: 2.8351x; 1.4039x over previous
#include <cuda_runtime.h>
#include <mma.h>

using namespace nvcuda;

namespace {
constexpr int NKEY = 49;
constexpr int QN_  = 196;
constexpr int DIM_ = 384;
constexpr int NH_  = 12;
constexpr int HD_  = 32;
constexpr int CQ_  = 192;
constexpr float SCALE_ = 0.17677669529663687f;  // 32^-0.5

constexpr int SKV    = 388;
constexpr int NT     = 384;   // 12 warps
constexpr int NW     = 12;
constexpr int CHUNK  = 16;
constexpr int STG_LD = 52;

// smem layout (floats)
constexpr int OFF_K   = 0;
constexpr int OFF_V   = OFF_K + NKEY * SKV;
constexpr int OFF_SCR = OFF_V + NKEY * SKV;
constexpr int SCR_SIZE = 19200;
constexpr int OFF_QC  = OFF_SCR + SCR_SIZE;
constexpr int SMEM_FLOATS = OFF_QC + CHUNK;   // 57,240 floats = 228,960 B

using FragA  = wmma::fragment<wmma::matrix_a, 16, 16, 8, wmma::precision::tf32, wmma::row_major>;
using FragBR = wmma::fragment<wmma::matrix_b, 16, 16, 8, wmma::precision::tf32, wmma::row_major>;
using FragBC = wmma::fragment<wmma::matrix_b, 16, 16, 8, wmma::precision::tf32, wmma::col_major>;
using FragC  = wmma::fragment<wmma::accumulator, 16, 16, 8, float>;

// fragment-packed weights: per fragment 32 lanes x 4 floats = 128 floats
constexpr int NF_KV   = 48 * 48;   // k-steps x n-tiles (768/16)
constexpr int NF_Q    = 24 * 24;   // (192/8) x (384/16)
constexpr int NF_PROJ = 48 * 12;   // (384/8) x (192/16)
}

__device__ float g_wkv_f [NF_KV   * 128];
__device__ float g_wq_f  [NF_Q    * 128];
__device__ float g_wp_f  [NF_PROJ * 128];
__device__ float g_bias_f[NH_ * 49 * NKEY];   // [h][qcell][key]

__device__ __forceinline__ float rtf(float x) { return wmma::__float_to_tf32(x); }

__device__ __forceinline__ void ld_packed_b(FragBR& f, const float* base, int lane) {
    const float4 v = ((const float4*)base)[lane];
    f.x[0] = v.x; f.x[1] = v.y; f.x[2] = v.z; f.x[3] = v.w;
}

// ---------------- setup kernels (run every launch; trivial cost) ----------------
__global__ void pack_weights(const float* __restrict__ w_kv,
                             const float* __restrict__ w_q,
                             const float* __restrict__ w_proj) {
    const int w    = blockIdx.x * 8 + (threadIdx.x >> 5);
    const int lane = threadIdx.x & 31;
    const float* src; int ld; float* dst;
    if (w < NF_KV) {
        const int ks = w / 48, nt = w - ks * 48;
        src = w_kv + ks * 8 * 768 + nt * 16; ld = 768; dst = g_wkv_f + w * 128;
    } else if (w < NF_KV + NF_Q) {
        const int w2 = w - NF_KV, ks = w2 / 24, nt = w2 - ks * 24;
        src = w_q + ks * 8 * DIM_ + nt * 16; ld = DIM_; dst = g_wq_f + w2 * 128;
    } else if (w < NF_KV + NF_Q + NF_PROJ) {
        const int w3 = w - NF_KV - NF_Q, ks = w3 / 12, nt = w3 - ks * 12;
        src = w_proj + ks * 8 * CQ_ + nt * 16; ld = CQ_; dst = g_wp_f + w3 * 128;
    } else return;
    FragBR f;
    wmma::load_matrix_sync(f, src, ld);
#pragma unroll
    for (int i = 0; i < 4; ++i) f.x[i] = rtf(f.x[i]);
    float4 v; v.x = f.x[0]; v.y = f.x[1]; v.z = f.x[2]; v.w = f.x[3];
    ((float4*)dst)[lane] = v;
}

__global__ void pack_bias(const float* __restrict__ bias_table) {
    const int idx = blockIdx.x * blockDim.x + threadIdx.x;
    if (idx >= NH_ * 49 * NKEY) return;
    const int h   = idx / (49 * NKEY);
    const int rem = idx - h * 49 * NKEY;
    const int qc  = rem / NKEY;          // (qi>>1)*7 + (qj>>1)
    const int key = rem - qc * NKEY;
    const int qi2 = qc / 7, qj2 = qc - qi2 * 7;
    const int kp  = key * 4;
    const int ki  = kp / 14, kj = kp - ki * 14;
    const int dh  = qi2 - (ki >> 1) + 6;
    const int dw  = qj2 - (kj >> 1) + 6;
    g_bias_f[idx] = bias_table[(dh * 13 + dw) * NH_ + h];
}

// ---------------- main kernel ----------------
__global__ __launch_bounds__(NT, 1)
void wca_kernel(const float* __restrict__ kv, const float* __restrict__ q,
                const float* __restrict__ w_kv, const float* __restrict__ b_kv,
                const float* __restrict__ b_q,
                const float* __restrict__ b_proj,
                float* __restrict__ out)
{
    extern __shared__ float sm[];
    float* s_k   = sm + OFF_K;
    float* s_v   = sm + OFF_V;
    float* s_x   = sm + OFF_SCR;
    float* s_qin = sm + OFF_SCR;
    float* s_qp  = sm + OFF_SCR + CHUNK * CQ_;
    float* s_stg = sm + OFF_SCR + CHUNK * CQ_ + CHUNK * DIM_;
    int*   s_qc  = (int*)(sm + OFF_QC);

    const int b    = blockIdx.x;
    const int tid  = threadIdx.x;
    const int wid  = tid >> 5;
    const int lane = tid & 31;

    // ---- phase 0: load + tf32-round kv input X (49x384) ----
    {
        const float4* src = (const float4*)(kv + (size_t)b * NKEY * DIM_);
        for (int i = tid; i < NKEY * DIM_ / 4; i += NT) {
            float4 v = src[i];
            v.x = rtf(v.x); v.y = rtf(v.y); v.z = rtf(v.z); v.w = rtf(v.w);
            ((float4*)s_x)[i] = v;
        }
    }
    __syncthreads();

    // ---- phase 1: kv projection rows 0..47 via wmma ----
    for (int j = wid; j < 24; j += NW) {
        const int m = j >> 3;
        const int nt0 = (j & 7) * 6;
        FragC c[6];
#pragma unroll
        for (int t = 0; t < 6; ++t) wmma::fill_fragment(c[t], 0.0f);
        for (int ks = 0; ks < 48; ++ks) {
            FragA a;
            wmma::load_matrix_sync(a, s_x + m * 16 * DIM_ + ks * 8, DIM_);
#pragma unroll
            for (int t = 0; t < 6; ++t) {
                FragBR bf;
                ld_packed_b(bf, g_wkv_f + (ks * 48 + nt0 + t) * 128, lane);
                wmma::mma_sync(c[t], a, bf, c[t]);
            }
        }
#pragma unroll
        for (int t = 0; t < 6; ++t) {
            const int col = (nt0 + t) * 16;
            float* dst = (col < DIM_) ? (s_k + m * 16 * SKV + col)
                                      : (s_v + m * 16 * SKV + (col - DIM_));
            wmma::store_matrix_sync(dst, c[t], SKV, wmma::mem_row_major);
        }
    }
    __syncthreads();

    // bias add + tf32 round rows 0..47; scalar row 48
    for (int i = tid; i < 48 * 768; i += NT) {
        const int r = i / 768, cc = i - r * 768;
        if (cc < DIM_) s_k[r * SKV + cc] = rtf(s_k[r * SKV + cc] + b_kv[cc]);
        else           s_v[r * SKV + cc - DIM_] = rtf(s_v[r * SKV + cc - DIM_] + b_kv[cc]);
    }
    {
        const float* x48 = s_x + 48 * DIM_;
        for (int cc = tid; cc < 768; cc += NT) {
            float acc = b_kv[cc];
#pragma unroll 4
            for (int k = 0; k < DIM_; ++k) acc = fmaf(x48[k], w_kv[k * 768 + cc], acc);
            if (cc < DIM_) s_k[48 * SKV + cc] = rtf(acc);
            else           s_v[48 * SKV + cc - DIM_] = rtf(acc);
        }
    }
    __syncthreads();

    // ---- phase 2: q chunks of 16 rows ----
    for (int q0 = 0; q0 < QN_; q0 += CHUNK) {
        const int nr = min(CHUNK, QN_ - q0);

        // 2a: load + round q chunk; compute q-cell per row
        {
            const float4* src = (const float4*)(q + (size_t)b * QN_ * CQ_ + (size_t)q0 * CQ_);
            const int lim = nr * CQ_ / 4;
            for (int i = tid; i < CHUNK * CQ_ / 4; i += NT) {
                float4 v = make_float4(0.f, 0.f, 0.f, 0.f);
                if (i < lim) {
                    v = src[i];
                    v.x = rtf(v.x); v.y = rtf(v.y); v.z = rtf(v.z); v.w = rtf(v.w);
                }
                ((float4*)s_qin)[i] = v;
            }
            if (tid < CHUNK) {
                const int qr = min(q0 + tid, QN_ - 1);
                const int qi = qr / 14, qj = qr - qi * 14;
                s_qc[tid] = (qi >> 1) * 7 + (qj >> 1);
            }
        }
        __syncthreads();

        // 2b: q projection; warp -> 32 cols
        {
            const int nt0 = wid * 2;
            FragC c[2];
            wmma::fill_fragment(c[0], 0.0f);
            wmma::fill_fragment(c[1], 0.0f);
            for (int ks = 0; ks < 24; ++ks) {
                FragA a;
                wmma::load_matrix_sync(a, s_qin + ks * 8, CQ_);
#pragma unroll
                for (int t = 0; t < 2; ++t) {
                    FragBR bf;
                    ld_packed_b(bf, g_wq_f + (ks * 24 + nt0 + t) * 128, lane);
                    wmma::mma_sync(c[t], a, bf, c[t]);
                }
            }
            wmma::store_matrix_sync(s_qp + nt0 * 16,      c[0], DIM_, wmma::mem_row_major);
            wmma::store_matrix_sync(s_qp + nt0 * 16 + 16, c[1], DIM_, wmma::mem_row_major);
        }
        __syncthreads();
        // bias + fold SCALE + round
        for (int i = tid; i < CHUNK * DIM_; i += NT)
            s_qp[i] = rtf((s_qp[i] + b_q[i % DIM_]) * SCALE_);
        __syncthreads();

        // 2c: attention — warp wid = head wid
        {
            const int h = wid;
            const int base = h * HD_;
            float* stg = s_stg + wid * (CHUNK * STG_LD);

            FragC s[3];
#pragma unroll
            for (int t = 0; t < 3; ++t) wmma::fill_fragment(s[t], 0.0f);
#pragma unroll
            for (int ks = 0; ks < 4; ++ks) {
                FragA a;
                wmma::load_matrix_sync(a, s_qp + base + ks * 8, DIM_);
#pragma unroll
                for (int t = 0; t < 3; ++t) {
                    FragBC bk;
                    wmma::load_matrix_sync(bk, s_k + (t * 16) * SKV + base + ks * 8, SKV);
                    wmma::mma_sync(s[t], a, bk, s[t]);
                }
            }
#pragma unroll
            for (int t = 0; t < 3; ++t)
                wmma::store_matrix_sync(stg + t * 16, s[t], STG_LD, wmma::mem_row_major);

            // key-48 logits (Q already scaled)
            if (lane < CHUNK) {
                float acc = 0.f;
                const float* qrow = s_qp + lane * DIM_ + base;
                const float* k48  = s_k + 48 * SKV + base;
#pragma unroll
                for (int d = 0; d < HD_; ++d) acc = fmaf(qrow[d], k48[d], acc);
                stg[lane * STG_LD + 48] = acc;
            }
            __syncwarp();

            // softmax, 2 lanes/row; p (tf32-rounded) in cols 0..48, 1/sum in col 49
            {
                const int r = lane >> 1, par = lane & 1;
                float* row = stg + r * STG_LD;
                const float* brow = g_bias_f + (h * 49 + s_qc[r]) * NKEY;
                float mx = -1e30f;
                for (int c = par; c < NKEY; c += 2) {
                    const float vv = row[c] + brow[c];
                    row[c] = vv;
                    mx = fmaxf(mx, vv);
                }
                mx = fmaxf(mx, __shfl_xor_sync(0xffffffffu, mx, 1));
                float ssum = 0.f;
                for (int c = par; c < NKEY; c += 2) {
                    const float p = __expf(row[c] - mx);
                    row[c] = rtf(p);
                    ssum += p;
                }
                ssum += __shfl_xor_sync(0xffffffffu, ssum, 1);
                if (par == 0) row[49] = 1.0f / ssum;
            }
            __syncwarp();

            // O = P @ V (keys 0..47 via wmma)
            FragC o[2];
            wmma::fill_fragment(o[0], 0.0f);
            wmma::fill_fragment(o[1], 0.0f);
#pragma unroll
            for (int ks = 0; ks < 6; ++ks) {
                FragA a;
                wmma::load_matrix_sync(a, stg + ks * 8, STG_LD);
#pragma unroll
                for (int t = 0; t < 2; ++t) {
                    FragBR bv;
                    wmma::load_matrix_sync(bv, s_v + ks * 8 * SKV + base + t * 16, SKV);
                    wmma::mma_sync(o[t], a, bv, o[t]);
                }
            }
            wmma::store_matrix_sync(s_qp + base,      o[0], DIM_, wmma::mem_row_major);
            wmma::store_matrix_sync(s_qp + base + 16, o[1], DIM_, wmma::mem_row_major);
            __syncwarp();

            // epilogue: add key-48, normalize, round for out-proj mma
            {
                const int r = lane >> 1, d0 = (lane & 1) * 16;
                const float p48 = stg[r * STG_LD + 48];
                const float inv = stg[r * STG_LD + 49];
                float* orow = s_qp + r * DIM_ + base + d0;
                const float* v48 = s_v + 48 * SKV + base + d0;
#pragma unroll
                for (int d = 0; d < 16; ++d)
                    orow[d] = rtf((orow[d] + p48 * v48[d]) * inv);
            }
        }
        __syncthreads();

        // 2d: out projection; warp -> 16 cols
        {
            FragC c;
            wmma::fill_fragment(c, 0.0f);
            for (int ks = 0; ks < 48; ++ks) {
                FragA a;
                wmma::load_matrix_sync(a, s_qp + ks * 8, DIM_);
                FragBR bw;
                ld_packed_b(bw, g_wp_f + (ks * 12 + wid) * 128, lane);
                wmma::mma_sync(c, a, bw, c);
            }
            wmma::store_matrix_sync(s_qin + wid * 16, c, CQ_, wmma::mem_row_major);
        }
        __syncthreads();

        // copy to gmem with bias
        {
            float4* ob = (float4*)(out + (size_t)b * QN_ * CQ_ + (size_t)q0 * CQ_);
            for (int i = tid; i < nr * CQ_ / 4; i += NT) {
                float4 v = ((float4*)s_qin)[i];
                const int j4 = (i * 4) % CQ_;
                const float4 bp = *(const float4*)(b_proj + j4);
                v.x += bp.x; v.y += bp.y; v.z += bp.z; v.w += bp.w;
                ob[i] = v;
            }
        }
        __syncthreads();
    }
}

extern "C" void kernel_launch(void* const* d_in, const int* in_sizes, int n_in,
                              void* d_out, int out_size) {
    const float* kv         = (const float*)d_in[0];
    const float* q          = (const float*)d_in[1];
    const float* w_kv       = (const float*)d_in[2];
    const float* b_kv       = (const float*)d_in[3];
    const float* w_q        = (const float*)d_in[4];
    const float* b_q        = (const float*)d_in[5];
    const float* bias_table = (const float*)d_in[6];
    const float* w_proj     = (const float*)d_in[7];
    const float* b_proj     = (const float*)d_in[8];
    float* out = (float*)d_out;

    const int B = in_sizes[0] / (NKEY * DIM_);               // 2048
    const int total_warps = NF_KV + NF_Q + NF_PROJ;          // 3456
    pack_weights<<<(total_warps + 7) / 8, 256>>>(w_kv, w_q, w_proj);
    pack_bias<<<(NH_ * 49 * NKEY + 511) / 512, 512>>>(bias_table);

    const size_t smem = (size_t)SMEM_FLOATS * sizeof(float); // 228,960 B
    cudaFuncSetAttribute(wca_kernel, cudaFuncAttributeMaxDynamicSharedMemorySize, (int)smem);
    wca_kernel<<<B, NT, smem>>>(kv, q, w_kv, b_kv, b_q, b_proj, out);
}

// round 6
// speedup vs baseline: 4.2797x; 1.5096x over previous
#include <cuda_runtime.h>
#include <cuda_fp16.h>
#include <mma.h>
#include <cstdint>

using namespace nvcuda;

namespace {
constexpr int NKEY = 49;
constexpr int QN_  = 196;
constexpr int DIM_ = 384;
constexpr int NH_  = 12;
constexpr int HD_  = 32;
constexpr int CQ_  = 192;
constexpr float SCALE_ = 0.17677669529663687f;

constexpr int NT    = 384;      // 12 warps
constexpr int NW    = 12;
constexpr int CHUNK = 32;
constexpr int SKVH  = 392;      // K/V row stride in halves (mult of 8)
constexpr int STGF  = 52;       // per-row staging stride in floats

// smem layout (bytes)
constexpr int OFF_K   = 0;                         // 49*392*2 = 38416
constexpr int OFF_V   = 38416;
constexpr int OFF_SCR = 76832;
constexpr int SZ_QIN  = 24576;                     // qin (half 32x192) / outstage (f32 32x192)
constexpr int SZ_QP   = 24576;                     // qp half 32x384
constexpr int OFF_QP  = OFF_SCR + SZ_QIN;
constexpr int OFF_STG = OFF_QP + SZ_QP;            // 12 warps * 32*52*4 = 79872
constexpr int OFF_QC  = OFF_STG + NW * CHUNK * STGF * 4;
constexpr int SMEM_BYTES = OFF_QC + CHUNK * 4;     // 205,984 B

using FragA  = wmma::fragment<wmma::matrix_a, 16, 16, 16, __half, wmma::row_major>;
using FragBR = wmma::fragment<wmma::matrix_b, 16, 16, 16, __half, wmma::row_major>;
using FragBC = wmma::fragment<wmma::matrix_b, 16, 16, 16, __half, wmma::col_major>;
using FragC  = wmma::fragment<wmma::accumulator, 16, 16, 16, float>;

constexpr int NF_KV = 24 * 48;   // (384/16 k-steps) x (768/16 n-tiles)
constexpr int NF_Q  = 12 * 24;
constexpr int NF_P  = 24 * 12;
}

__device__ __half g_wkv_h[DIM_ * 768];
__device__ __half g_wq_h [CQ_ * DIM_];
__device__ __half g_wp_h [DIM_ * CQ_];
__device__ uint4  g_wkv_f[NF_KV * 32];
__device__ uint4  g_wq_f [NF_Q  * 32];
__device__ uint4  g_wp_f [NF_P  * 32];
__device__ float  g_bias_f[NH_ * 49 * NKEY];

__device__ __forceinline__ void ld_packed_b(FragBR& f, const uint4* base, int lane) {
    const uint4 v = base[lane];
    unsigned int w[4] = {v.x, v.y, v.z, v.w};
#pragma unroll
    for (int i = 0; i < 4; ++i) {
        const __half2 h2 = *reinterpret_cast<const __half2*>(&w[i]);
        f.x[2 * i]     = __low2half(h2);
        f.x[2 * i + 1] = __high2half(h2);
    }
}

// ---------------- setup kernels ----------------
__global__ void cvt_weights(const float* __restrict__ w_kv,
                            const float* __restrict__ w_q,
                            const float* __restrict__ w_proj) {
    const int i = blockIdx.x * blockDim.x + threadIdx.x;
    if (i < DIM_ * 768) g_wkv_h[i] = __float2half_rn(w_kv[i]);
    if (i < CQ_ * DIM_) g_wq_h[i]  = __float2half_rn(w_q[i]);
    if (i < DIM_ * CQ_) g_wp_h[i]  = __float2half_rn(w_proj[i]);
}

__global__ void pack_frags() {
    const int w    = blockIdx.x * 8 + (threadIdx.x >> 5);
    const int lane = threadIdx.x & 31;
    const __half* src; int ld; uint4* dst;
    if (w < NF_KV) {
        const int ks = w / 48, nt = w - ks * 48;
        src = g_wkv_h + ks * 16 * 768 + nt * 16; ld = 768; dst = g_wkv_f + w * 32;
    } else if (w < NF_KV + NF_Q) {
        const int w2 = w - NF_KV, ks = w2 / 24, nt = w2 - ks * 24;
        src = g_wq_h + ks * 16 * DIM_ + nt * 16; ld = DIM_; dst = g_wq_f + w2 * 32;
    } else if (w < NF_KV + NF_Q + NF_P) {
        const int w3 = w - NF_KV - NF_Q, ks = w3 / 12, nt = w3 - ks * 12;
        src = g_wp_h + ks * 16 * CQ_ + nt * 16; ld = CQ_; dst = g_wp_f + w3 * 32;
    } else return;
    FragBR f;
    wmma::load_matrix_sync(f, src, ld);
    unsigned int w4[4];
#pragma unroll
    for (int i = 0; i < 4; ++i) {
        __half2 h2 = __halves2half2(f.x[2 * i], f.x[2 * i + 1]);
        w4[i] = *reinterpret_cast<unsigned int*>(&h2);
    }
    dst[lane] = make_uint4(w4[0], w4[1], w4[2], w4[3]);
}

__global__ void pack_bias(const float* __restrict__ bias_table) {
    const int idx = blockIdx.x * blockDim.x + threadIdx.x;
    if (idx >= NH_ * 49 * NKEY) return;
    const int h   = idx / (49 * NKEY);
    const int rem = idx - h * 49 * NKEY;
    const int qc  = rem / NKEY;
    const int key = rem - qc * NKEY;
    const int qi2 = qc / 7, qj2 = qc - qi2 * 7;
    const int kp  = key * 4;
    const int ki  = kp / 14, kj = kp - ki * 14;
    const int dh  = qi2 - (ki >> 1) + 6;
    const int dw  = qj2 - (kj >> 1) + 6;
    g_bias_f[idx] = bias_table[(dh * 13 + dw) * NH_ + h];
}

// ---------------- main kernel ----------------
__global__ __launch_bounds__(NT, 1)
void wca_kernel(const float* __restrict__ kv, const float* __restrict__ q,
                const float* __restrict__ w_kv, const float* __restrict__ b_kv,
                const float* __restrict__ b_q,
                const float* __restrict__ b_proj,
                float* __restrict__ out)
{
    extern __shared__ char smb[];
    __half* s_k   = (__half*)(smb + OFF_K);
    __half* s_v   = (__half*)(smb + OFF_V);
    __half* s_x   = (__half*)(smb + OFF_SCR);       // phase 1: kv input 49x384
    __half* s_qin = (__half*)(smb + OFF_SCR);       // chunk: q input 32x192
    float*  s_ost = (float*)(smb + OFF_SCR);        // chunk 2d: out staging 32x192 f32
    __half* s_qp  = (__half*)(smb + OFF_QP);        // 32x384 half
    float*  s_stg = (float*)(smb + OFF_STG);        // 12 warps x 32 x STGF f32
    int*    s_qc  = (int*)(smb + OFF_QC);

    const int b    = blockIdx.x;
    const int tid  = threadIdx.x;
    const int wid  = tid >> 5;
    const int lane = tid & 31;
    float* wstg = s_stg + wid * (CHUNK * STGF);

    // ---- phase 0: load kv input -> half ----
    {
        const float4* src = (const float4*)(kv + (size_t)b * NKEY * DIM_);
        for (int i = tid; i < NKEY * DIM_ / 4; i += NT) {
            const float4 v = src[i];
            __half2 h0 = __floats2half2_rn(v.x, v.y);
            __half2 h1 = __floats2half2_rn(v.z, v.w);
            ((__half2*)s_x)[2 * i]     = h0;
            ((__half2*)s_x)[2 * i + 1] = h1;
        }
    }
    __syncthreads();

    // ---- phase 1: kv projection rows 0..47 ----
    {
        const int m  = wid >> 2;          // 0..2
        const int ng = wid & 3;           // 0..3 -> n-tiles ng*12 .. +12
        for (int pass = 0; pass < 2; ++pass) {
            FragC c[6];
#pragma unroll
            for (int t = 0; t < 6; ++t) wmma::fill_fragment(c[t], 0.0f);
            for (int ks = 0; ks < 24; ++ks) {
                FragA a;
                wmma::load_matrix_sync(a, s_x + m * 16 * DIM_ + ks * 16, DIM_);
#pragma unroll
                for (int t = 0; t < 6; ++t) {
                    FragBR bf;
                    ld_packed_b(bf, g_wkv_f + (ks * 48 + ng * 12 + pass * 6 + t) * 32, lane);
                    wmma::mma_sync(c[t], a, bf, c[t]);
                }
            }
#pragma unroll
            for (int t = 0; t < 6; ++t)
                wmma::store_matrix_sync(wstg + t * 256, c[t], 16, wmma::mem_row_major);
            __syncwarp();
            // convert + bias -> s_k / s_v (6*256 = 1536 elems, 48/lane)
            for (int e = lane; e < 1536; e += 32) {
                const int t = e >> 8, idx = e & 255;
                const int row = idx >> 4, col = idx & 15;
                const int colg = (ng * 12 + pass * 6 + t) * 16 + col;
                const float v = wstg[t * 256 + idx] + b_kv[colg];
                const int rg = m * 16 + row;
                if (colg < DIM_) s_k[rg * SKVH + colg] = __float2half_rn(v);
                else             s_v[rg * SKVH + colg - DIM_] = __float2half_rn(v);
            }
            __syncwarp();
        }
    }
    // row 48 scalar
    {
        const __half* x48 = s_x + 48 * DIM_;
        for (int cc = tid; cc < 768; cc += NT) {
            float acc = b_kv[cc];
#pragma unroll 4
            for (int k = 0; k < DIM_; ++k)
                acc = fmaf(__half2float(x48[k]), w_kv[k * 768 + cc], acc);
            if (cc < DIM_) s_k[48 * SKVH + cc] = __float2half_rn(acc);
            else           s_v[48 * SKVH + cc - DIM_] = __float2half_rn(acc);
        }
    }
    __syncthreads();

    // ---- phase 2: q chunks of 32 rows ----
    for (int q0 = 0; q0 < QN_; q0 += CHUNK) {
        const int nr = min(CHUNK, QN_ - q0);

        // 2a: load q chunk -> half (zero-pad), q-cells
        {
            const float4* src = (const float4*)(q + (size_t)b * QN_ * CQ_ + (size_t)q0 * CQ_);
            const int lim = nr * CQ_ / 4;
            for (int i = tid; i < CHUNK * CQ_ / 4; i += NT) {
                float4 v = make_float4(0.f, 0.f, 0.f, 0.f);
                if (i < lim) v = src[i];
                ((__half2*)s_qin)[2 * i]     = __floats2half2_rn(v.x, v.y);
                ((__half2*)s_qin)[2 * i + 1] = __floats2half2_rn(v.z, v.w);
            }
            if (tid < CHUNK) {
                const int qr = min(q0 + tid, QN_ - 1);
                const int qi = qr / 14, qj = qr - qi * 14;
                s_qc[tid] = (qi >> 1) * 7 + (qj >> 1);
            }
        }
        __syncthreads();

        // 2b: q projection — warp = (m = wid/6, ng = wid%6) -> 4 n-tiles
        {
            const int m = wid / 6, ng = wid % 6;
            FragC c[4];
#pragma unroll
            for (int t = 0; t < 4; ++t) wmma::fill_fragment(c[t], 0.0f);
            for (int ks = 0; ks < 12; ++ks) {
                FragA a;
                wmma::load_matrix_sync(a, s_qin + m * 16 * CQ_ + ks * 16, CQ_);
#pragma unroll
                for (int t = 0; t < 4; ++t) {
                    FragBR bf;
                    ld_packed_b(bf, g_wq_f + (ks * 24 + ng * 4 + t) * 32, lane);
                    wmma::mma_sync(c[t], a, bf, c[t]);
                }
            }
#pragma unroll
            for (int t = 0; t < 4; ++t)
                wmma::store_matrix_sync(wstg + t * 256, c[t], 16, wmma::mem_row_major);
            __syncwarp();
            for (int e = lane; e < 1024; e += 32) {
                const int t = e >> 8, idx = e & 255;
                const int row = idx >> 4, col = idx & 15;
                const int colg = (ng * 4 + t) * 16 + col;
                const float v = (wstg[t * 256 + idx] + b_q[colg]) * SCALE_;
                s_qp[(m * 16 + row) * DIM_ + colg] = __float2half_rn(v);
            }
        }
        __syncthreads();

        // 2c: attention — warp wid = head
        {
            const int h = wid;
            const int base = h * HD_;

            // S = Q Kt : 2m x 3n x 2ks
            FragC s[2][3];
#pragma unroll
            for (int m = 0; m < 2; ++m)
#pragma unroll
                for (int t = 0; t < 3; ++t) wmma::fill_fragment(s[m][t], 0.0f);
#pragma unroll
            for (int ks = 0; ks < 2; ++ks) {
                FragA a0, a1;
                wmma::load_matrix_sync(a0, s_qp + base + ks * 16, DIM_);
                wmma::load_matrix_sync(a1, s_qp + 16 * DIM_ + base + ks * 16, DIM_);
#pragma unroll
                for (int t = 0; t < 3; ++t) {
                    FragBC bk;
                    wmma::load_matrix_sync(bk, s_k + (t * 16) * SKVH + base + ks * 16, SKVH);
                    wmma::mma_sync(s[0][t], a0, bk, s[0][t]);
                    wmma::mma_sync(s[1][t], a1, bk, s[1][t]);
                }
            }
#pragma unroll
            for (int m = 0; m < 2; ++m)
#pragma unroll
                for (int t = 0; t < 3; ++t)
                    wmma::store_matrix_sync(wstg + m * 16 * STGF + t * 16, s[m][t],
                                            STGF, wmma::mem_row_major);

            // key-48 logit, lane = row
            {
                float acc = 0.f;
                const __half* qrow = s_qp + lane * DIM_ + base;
                const __half* k48  = s_k + 48 * SKVH + base;
#pragma unroll
                for (int d = 0; d < HD_; ++d)
                    acc = fmaf(__half2float(qrow[d]), __half2float(k48[d]), acc);
                wstg[lane * STGF + 48] = acc;
            }
            __syncwarp();

            // softmax, lane = row; write p as half aliased over S (cols 0..47),
            // p48 -> f32 col 50, 1/sum -> f32 col 51
            {
                float* row = wstg + lane * STGF;
                __half* prow = (__half*)row;
                const float* brow = g_bias_f + (h * 49 + s_qc[lane]) * NKEY;
                float mx = -1e30f;
#pragma unroll 7
                for (int c = 0; c < NKEY; ++c) {
                    const float vv = row[c] + brow[c];
                    row[c] = vv;
                    mx = fmaxf(mx, vv);
                }
                float ssum = 0.f;
#pragma unroll 7
                for (int c = 0; c < NKEY; ++c) {
                    const float p = __expf(row[c] - mx);
                    ssum += p;
                    if (c < 48) prow[c] = __float2half_rn(p);
                    else        row[50] = p;
                }
                row[51] = 1.0f / ssum;
            }
            __syncwarp();

            // O = P V : 2m x 2n x 3ks ; A = half P stride 104
            FragC o[2][2];
#pragma unroll
            for (int m = 0; m < 2; ++m)
#pragma unroll
                for (int t = 0; t < 2; ++t) wmma::fill_fragment(o[m][t], 0.0f);
#pragma unroll
            for (int ks = 0; ks < 3; ++ks) {
                FragA a0, a1;
                wmma::load_matrix_sync(a0, (__half*)wstg + ks * 16, STGF * 2);
                wmma::load_matrix_sync(a1, (__half*)wstg + 16 * STGF * 2 + ks * 16, STGF * 2);
#pragma unroll
                for (int t = 0; t < 2; ++t) {
                    FragBR bv;
                    wmma::load_matrix_sync(bv, s_v + ks * 16 * SKVH + base + t * 16, SKVH);
                    wmma::mma_sync(o[0][t], a0, bv, o[0][t]);
                    wmma::mma_sync(o[1][t], a1, bv, o[1][t]);
                }
            }
#pragma unroll
            for (int m = 0; m < 2; ++m)
#pragma unroll
                for (int t = 0; t < 2; ++t)
                    wmma::store_matrix_sync(wstg + m * 16 * STGF + t * 16, o[m][t],
                                            STGF, wmma::mem_row_major);
            __syncwarp();

            // epilogue: lane = row
            {
                float* row = wstg + lane * STGF;
                const float p48 = row[50];
                const float inv = row[51];
                const __half* v48 = s_v + 48 * SKVH + base;
                __half* dst = s_qp + lane * DIM_ + base;
#pragma unroll
                for (int d = 0; d < HD_; ++d) {
                    const float v = (row[d] + p48 * __half2float(v48[d])) * inv;
                    dst[d] = __float2half_rn(v);
                }
            }
        }
        __syncthreads();

        // 2d: out projection — warp = (m = wid/6, ng = wid%6) -> 2 n-tiles
        {
            const int m = wid / 6, ng = wid % 6;
            FragC c[2];
            wmma::fill_fragment(c[0], 0.0f);
            wmma::fill_fragment(c[1], 0.0f);
            for (int ks = 0; ks < 24; ++ks) {
                FragA a;
                wmma::load_matrix_sync(a, s_qp + m * 16 * DIM_ + ks * 16, DIM_);
#pragma unroll
                for (int t = 0; t < 2; ++t) {
                    FragBR bw;
                    ld_packed_b(bw, g_wp_f + (ks * 12 + ng * 2 + t) * 32, lane);
                    wmma::mma_sync(c[t], a, bw, c[t]);
                }
            }
#pragma unroll
            for (int t = 0; t < 2; ++t)
                wmma::store_matrix_sync(s_ost + m * 16 * CQ_ + (ng * 2 + t) * 16,
                                        c[t], CQ_, wmma::mem_row_major);
        }
        __syncthreads();

        // write to gmem with bias
        {
            float4* ob = (float4*)(out + (size_t)b * QN_ * CQ_ + (size_t)q0 * CQ_);
            for (int i = tid; i < nr * CQ_ / 4; i += NT) {
                float4 v = ((float4*)s_ost)[i];
                const int j4 = (i * 4) % CQ_;
                const float4 bp = *(const float4*)(b_proj + j4);
                v.x += bp.x; v.y += bp.y; v.z += bp.z; v.w += bp.w;
                ob[i] = v;
            }
        }
        __syncthreads();
    }
}

extern "C" void kernel_launch(void* const* d_in, const int* in_sizes, int n_in,
                              void* d_out, int out_size) {
    const float* kv         = (const float*)d_in[0];
    const float* q          = (const float*)d_in[1];
    const float* w_kv       = (const float*)d_in[2];
    const float* b_kv       = (const float*)d_in[3];
    const float* w_q        = (const float*)d_in[4];
    const float* b_q        = (const float*)d_in[5];
    const float* bias_table = (const float*)d_in[6];
    const float* w_proj     = (const float*)d_in[7];
    const float* b_proj     = (const float*)d_in[8];
    float* out = (float*)d_out;

    const int B = in_sizes[0] / (NKEY * DIM_);              // 2048
    cvt_weights<<<(DIM_ * 768 + 255) / 256, 256>>>(w_kv, w_q, w_proj);
    const int nfrag = NF_KV + NF_Q + NF_P;                  // 1728
    pack_frags<<<(nfrag + 7) / 8, 256>>>();
    pack_bias<<<(NH_ * 49 * NKEY + 511) / 512, 512>>>(bias_table);

    cudaFuncSetAttribute(wca_kernel, cudaFuncAttributeMaxDynamicSharedMemorySize, SMEM_BYTES);
    wca_kernel<<<B, NT, SMEM_BYTES>>>(kv, q, w_kv, b_kv, b_q, b_proj, out);
}

// round 7
// speedup vs baseline: 11.4504x; 2.6755x over previous
#include <cuda_runtime.h>
#include <cuda_fp16.h>
#include <mma.h>
#include <cstdint>

using namespace nvcuda;

namespace {
constexpr int NKEY = 49;
constexpr int QN_  = 196;
constexpr int DIM_ = 384;
constexpr int NH_  = 12;
constexpr int HD_  = 32;
constexpr int CQ_  = 192;
constexpr float SCALE_ = 0.17677669529663687f;

constexpr int NT   = 384;    // 12 warps
constexpr int NW   = 12;
constexpr int CHUNK = 32;
constexpr int SUB   = 16;    // attention sub-chunk rows
constexpr int NKP   = 64;    // padded keys / kv rows

constexpr int SKVH = 392;    // K/V row stride (halves): 784B, 16B phase shift
constexpr int SQP  = 392;    // qp / x stride (halves)
constexpr int SQIN = 200;    // q-input stride (halves): 400B
constexpr int STGF = 68;     // staging stride (f32): 272B

// smem byte offsets
constexpr int SZ_KV   = NKP * SKVH * 2;              // 50176
constexpr int OFF_K   = 0;
constexpr int OFF_V   = OFF_K + SZ_KV;
constexpr int OFF_SCR = OFF_V + SZ_KV;               // 100352
constexpr int OFF_QP  = OFF_SCR + 24576;             // after qin/ost region
constexpr int SCR_SIZE = 50176;                      // covers s_x 64x392 half
constexpr int OFF_STG = OFF_SCR + SCR_SIZE;          // 150528
constexpr int SZ_STG  = NW * SUB * STGF * 4;         // 52224
constexpr int OFF_QC  = OFF_STG + SZ_STG;            // 202752
constexpr int OFF_ONE = OFF_QC + CHUNK * 4;          // 202880
constexpr int SMEM_BYTES = OFF_ONE + 512;            // 203392

using FragA  = wmma::fragment<wmma::matrix_a, 16, 16, 16, __half, wmma::row_major>;
using FragBR = wmma::fragment<wmma::matrix_b, 16, 16, 16, __half, wmma::row_major>;
using FragBC = wmma::fragment<wmma::matrix_b, 16, 16, 16, __half, wmma::col_major>;
using FragC  = wmma::fragment<wmma::accumulator, 16, 16, 16, float>;
using FragCH = wmma::fragment<wmma::accumulator, 16, 16, 16, __half>;

constexpr int NF_KV = 25 * 48;   // 24 k-steps + bias step, 48 n-tiles
constexpr int NF_Q  = 13 * 24;   // 12 + bias, 24 n-tiles
constexpr int NF_P  = 25 * 12;   // 24 + bias, 12 n-tiles
}

__device__ uint4 g_wkv_f[NF_KV * 32];
__device__ uint4 g_wq_f [NF_Q  * 32];
__device__ uint4 g_wp_f [NF_P  * 32];
__device__ float g_bias_f[NH_ * 49 * NKEY];

__device__ __forceinline__ void ld_packed_b(FragBR& f, const uint4* base, int lane) {
    const uint4 v = base[lane];
    unsigned int w[4] = {v.x, v.y, v.z, v.w};
#pragma unroll
    for (int i = 0; i < 4; ++i) {
        const __half2 h2 = *reinterpret_cast<const __half2*>(&w[i]);
        f.x[2 * i]     = __low2half(h2);
        f.x[2 * i + 1] = __high2half(h2);
    }
}

__device__ __forceinline__ void cvt_store_half(__half* dst, int ld, const FragC& c) {
    FragCH h;
#pragma unroll
    for (int i = 0; i < 8; ++i) h.x[i] = __float2half_rn(c.x[i]);
    wmma::store_matrix_sync(dst, h, ld, wmma::mem_row_major);
}

// ---------------- setup kernels ----------------
__global__ void pack_frags(const float* __restrict__ w_kv, const float* __restrict__ b_kv,
                           const float* __restrict__ w_q,  const float* __restrict__ b_q,
                           const float* __restrict__ w_proj, const float* __restrict__ b_proj) {
    __shared__ __half tiles[8][256];
    const int w    = blockIdx.x * 8 + (threadIdx.x >> 5);
    const int lane = threadIdx.x & 31;
    __half* tile = tiles[threadIdx.x >> 5];
    uint4* dst;
    if (w < NF_KV) {
        const int ks = w / 48, nt = w - ks * 48, n0 = nt * 16;
        for (int e = lane; e < 256; e += 32) {
            const int r = e >> 4, c = e & 15;
            float v;
            if (ks < 24) v = w_kv[(ks * 16 + r) * 768 + n0 + c];
            else         v = (r == 0) ? b_kv[n0 + c] : 0.0f;
            tile[e] = __float2half_rn(v);
        }
        dst = g_wkv_f + w * 32;
    } else if (w < NF_KV + NF_Q) {
        const int w2 = w - NF_KV, ks = w2 / 24, nt = w2 - ks * 24, n0 = nt * 16;
        for (int e = lane; e < 256; e += 32) {
            const int r = e >> 4, c = e & 15;
            float v;
            if (ks < 12) v = w_q[(ks * 16 + r) * DIM_ + n0 + c] * SCALE_;
            else         v = (r == 0) ? b_q[n0 + c] * SCALE_ : 0.0f;
            tile[e] = __float2half_rn(v);
        }
        dst = g_wq_f + w2 * 32;
    } else if (w < NF_KV + NF_Q + NF_P) {
        const int w3 = w - NF_KV - NF_Q, ks = w3 / 12, nt = w3 - ks * 12, n0 = nt * 16;
        for (int e = lane; e < 256; e += 32) {
            const int r = e >> 4, c = e & 15;
            float v;
            if (ks < 24) v = w_proj[(ks * 16 + r) * CQ_ + n0 + c];
            else         v = (r == 0) ? b_proj[n0 + c] : 0.0f;
            tile[e] = __float2half_rn(v);
        }
        dst = g_wp_f + w3 * 32;
    } else return;
    __syncwarp();
    FragBR f;
    wmma::load_matrix_sync(f, tile, 16);
    unsigned int w4[4];
#pragma unroll
    for (int i = 0; i < 4; ++i) {
        __half2 h2 = __halves2half2(f.x[2 * i], f.x[2 * i + 1]);
        w4[i] = *reinterpret_cast<unsigned int*>(&h2);
    }
    dst[lane] = make_uint4(w4[0], w4[1], w4[2], w4[3]);
}

__global__ void pack_bias(const float* __restrict__ bias_table) {
    const int idx = blockIdx.x * blockDim.x + threadIdx.x;
    if (idx >= NH_ * 49 * NKEY) return;
    const int h   = idx / (49 * NKEY);
    const int rem = idx - h * 49 * NKEY;
    const int qc  = rem / NKEY;
    const int key = rem - qc * NKEY;
    const int qi2 = qc / 7, qj2 = qc - qi2 * 7;
    const int kp  = key * 4;
    const int ki  = kp / 14, kj = kp - ki * 14;
    const int dh  = qi2 - (ki >> 1) + 6;
    const int dw  = qj2 - (kj >> 1) + 6;
    g_bias_f[idx] = bias_table[(dh * 13 + dw) * NH_ + h];
}

// ---------------- main kernel ----------------
__global__ __launch_bounds__(NT, 1)
void wca_kernel(const float* __restrict__ kv, const float* __restrict__ q,
                float* __restrict__ out)
{
    extern __shared__ char smb[];
    __half* s_k   = (__half*)(smb + OFF_K);
    __half* s_v   = (__half*)(smb + OFF_V);
    __half* s_x   = (__half*)(smb + OFF_SCR);   // phase 1: 64x392 half
    __half* s_qin = (__half*)(smb + OFF_SCR);   // chunk: 32x200 half
    float*  s_ost = (float*)(smb + OFF_SCR);    // last chunk: 32x192 f32
    __half* s_qp  = (__half*)(smb + OFF_QP);    // 32x392 half
    float*  s_stg = (float*)(smb + OFF_STG);    // 12 x (16 x 68) f32
    int*    s_qc  = (int*)(smb + OFF_QC);
    __half* s_one = (__half*)(smb + OFF_ONE);   // 16x16 ones-column tile

    const int b    = blockIdx.x;
    const int tid  = threadIdx.x;
    const int wid  = tid >> 5;
    const int lane = tid & 31;
    float* wstg = s_stg + wid * (SUB * STGF);

    // ---- phase 0: X load (rows 0..48), zero pad rows, ones tile ----
    {
        const float4* src = (const float4*)(kv + (size_t)b * NKEY * DIM_);
        for (int i = tid; i < NKEY * 96; i += NT) {          // 96 float4 per row
            const int r = i / 96, c4 = (i - r * 96) * 4;
            const float4 v = src[i];
            __half* d = s_x + r * SQP + c4;
            d[0] = __float2half_rn(v.x); d[1] = __float2half_rn(v.y);
            d[2] = __float2half_rn(v.z); d[3] = __float2half_rn(v.w);
        }
        for (int i = tid; i < (NKP - NKEY) * SQP; i += NT)
            s_x[NKEY * SQP + i] = __float2half_rn(0.0f);
        if (tid < 256) s_one[tid] = __float2half_rn((tid & 15) == 0 ? 1.0f : 0.0f);
    }
    __syncthreads();

    // ---- phase 1: kv projection, 4 m-tiles x 48 n-tiles, bias as k-step ----
    {
        const int m = wid & 3;          // rows m*16..m*16+15 (m=3 covers pad)
        const int g = wid >> 2;         // 0..2 -> 16 n-tiles
        FragA ones;
        wmma::load_matrix_sync(ones, s_one, 16);
        for (int pass = 0; pass < 2; ++pass) {
            const int nt0 = g * 16 + pass * 8;
            FragC c[8];
#pragma unroll
            for (int t = 0; t < 8; ++t) wmma::fill_fragment(c[t], 0.0f);
            for (int ks = 0; ks < 24; ++ks) {
                FragA a;
                wmma::load_matrix_sync(a, s_x + m * 16 * SQP + ks * 16, SQP);
#pragma unroll
                for (int t = 0; t < 8; ++t) {
                    FragBR bf;
                    ld_packed_b(bf, g_wkv_f + (ks * 48 + nt0 + t) * 32, lane);
                    wmma::mma_sync(c[t], a, bf, c[t]);
                }
            }
#pragma unroll
            for (int t = 0; t < 8; ++t) {        // bias k-step
                FragBR bf;
                ld_packed_b(bf, g_wkv_f + (24 * 48 + nt0 + t) * 32, lane);
                wmma::mma_sync(c[t], ones, bf, c[t]);
            }
#pragma unroll
            for (int t = 0; t < 8; ++t) {
                const int colg = (nt0 + t) * 16;
                __half* dst = (colg < DIM_) ? (s_k + m * 16 * SKVH + colg)
                                            : (s_v + m * 16 * SKVH + colg - DIM_);
                cvt_store_half(dst, SKVH, c[t]);
            }
        }
    }
    __syncthreads();

    // ---- phase 2: q chunks of 32 rows ----
    for (int q0 = 0; q0 < QN_; q0 += CHUNK) {
        const int nr = min(CHUNK, QN_ - q0);

        // 2a: q chunk -> half (zero pad rows >= nr), q-cells
        {
            const float4* src = (const float4*)(q + (size_t)b * QN_ * CQ_ + (size_t)q0 * CQ_);
            for (int i = tid; i < CHUNK * 48; i += NT) {     // 48 float4 per row
                const int r = i / 48, c4 = (i - r * 48) * 4;
                float4 v = make_float4(0.f, 0.f, 0.f, 0.f);
                if (r < nr) v = src[i];
                __half* d = s_qin + r * SQIN + c4;
                d[0] = __float2half_rn(v.x); d[1] = __float2half_rn(v.y);
                d[2] = __float2half_rn(v.z); d[3] = __float2half_rn(v.w);
            }
            if (tid < CHUNK) {
                const int qr = min(q0 + tid, QN_ - 1);
                const int qi = qr / 14, qj = qr - qi * 14;
                s_qc[tid] = (qi >> 1) * 7 + (qj >> 1);
            }
        }
        __syncthreads();

        // 2b: q projection (scale+bias folded), direct half store
        {
            const int m = wid / 6, ng = (wid % 6) * 4;
            FragA ones;
            wmma::load_matrix_sync(ones, s_one, 16);
            FragC c[4];
#pragma unroll
            for (int t = 0; t < 4; ++t) wmma::fill_fragment(c[t], 0.0f);
            for (int ks = 0; ks < 12; ++ks) {
                FragA a;
                wmma::load_matrix_sync(a, s_qin + m * 16 * SQIN + ks * 16, SQIN);
#pragma unroll
                for (int t = 0; t < 4; ++t) {
                    FragBR bf;
                    ld_packed_b(bf, g_wq_f + (ks * 24 + ng + t) * 32, lane);
                    wmma::mma_sync(c[t], a, bf, c[t]);
                }
            }
#pragma unroll
            for (int t = 0; t < 4; ++t) {
                FragBR bf;
                ld_packed_b(bf, g_wq_f + (12 * 24 + ng + t) * 32, lane);
                wmma::mma_sync(c[t], ones, bf, c[t]);
                cvt_store_half(s_qp + m * 16 * SQP + (ng + t) * 16, SQP, c[t]);
            }
        }
        __syncthreads();

        // 2c: attention — warp = head; two 16-row sub-chunks
        {
            const int h = wid;
            const int base = h * HD_;
            for (int s = 0; s < 2; ++s) {
                const int r0 = s * 16;
                // S = Q Kt over 64 padded keys
                FragC sf[4];
#pragma unroll
                for (int t = 0; t < 4; ++t) wmma::fill_fragment(sf[t], 0.0f);
#pragma unroll
                for (int ks = 0; ks < 2; ++ks) {
                    FragA a;
                    wmma::load_matrix_sync(a, s_qp + r0 * SQP + base + ks * 16, SQP);
#pragma unroll
                    for (int t = 0; t < 4; ++t) {
                        FragBC bk;
                        wmma::load_matrix_sync(bk, s_k + (t * 16) * SKVH + base + ks * 16, SKVH);
                        wmma::mma_sync(sf[t], a, bk, sf[t]);
                    }
                }
#pragma unroll
                for (int t = 0; t < 4; ++t)
                    wmma::store_matrix_sync(wstg + t * 16, sf[t], STGF, wmma::mem_row_major);
                __syncwarp();

                // softmax: 2 lanes per row; write pre-normalized half P
                {
                    const int r = lane >> 1, par = lane & 1;
                    float* row = wstg + r * STGF;
                    const float* brow = g_bias_f + (h * 49 + s_qc[r0 + r]) * NKEY;
                    float vals[25];
                    int cnt = 0;
                    float mx = -1e30f;
                    for (int c = par; c < NKEY; c += 2) {
                        const float v = row[c] + brow[c];
                        vals[cnt++] = v;
                        mx = fmaxf(mx, v);
                    }
                    mx = fmaxf(mx, __shfl_xor_sync(0xffffffffu, mx, 1));
                    float ssum = 0.f;
                    for (int i = 0; i < cnt; ++i) {
                        const float p = __expf(vals[i] - mx);
                        vals[i] = p;
                        ssum += p;
                    }
                    ssum += __shfl_xor_sync(0xffffffffu, ssum, 1);
                    const float inv = 1.0f / ssum;
                    __half* prow = (__half*)wstg + r * (STGF * 2);
                    int i = 0;
                    for (int c = par; c < 64; c += 2) {
                        const float p = (c < NKEY) ? vals[i++] * inv : 0.0f;
                        prow[c] = __float2half_rn(p);
                    }
                }
                __syncwarp();

                // O = Pn V over 64 padded keys; direct half store
                FragC o[2];
                wmma::fill_fragment(o[0], 0.0f);
                wmma::fill_fragment(o[1], 0.0f);
#pragma unroll
                for (int ks = 0; ks < 4; ++ks) {
                    FragA a;
                    wmma::load_matrix_sync(a, (__half*)wstg + ks * 16, STGF * 2);
#pragma unroll
                    for (int t = 0; t < 2; ++t) {
                        FragBR bv;
                        wmma::load_matrix_sync(bv, s_v + ks * 16 * SKVH + base + t * 16, SKVH);
                        wmma::mma_sync(o[t], a, bv, o[t]);
                    }
                }
#pragma unroll
                for (int t = 0; t < 2; ++t)
                    cvt_store_half(s_qp + r0 * SQP + base + t * 16, SQP, o[t]);
                __syncwarp();
            }
        }
        __syncthreads();

        // 2d: out projection (bias folded); direct gmem store for full chunks
        {
            const int m = wid / 6, ng = (wid % 6) * 2;
            FragA ones;
            wmma::load_matrix_sync(ones, s_one, 16);
            FragC c[2];
            wmma::fill_fragment(c[0], 0.0f);
            wmma::fill_fragment(c[1], 0.0f);
            for (int ks = 0; ks < 24; ++ks) {
                FragA a;
                wmma::load_matrix_sync(a, s_qp + m * 16 * SQP + ks * 16, SQP);
#pragma unroll
                for (int t = 0; t < 2; ++t) {
                    FragBR bw;
                    ld_packed_b(bw, g_wp_f + (ks * 12 + ng + t) * 32, lane);
                    wmma::mma_sync(c[t], a, bw, c[t]);
                }
            }
#pragma unroll
            for (int t = 0; t < 2; ++t) {
                FragBR bw;
                ld_packed_b(bw, g_wp_f + (24 * 12 + ng + t) * 32, lane);
                wmma::mma_sync(c[t], ones, bw, c[t]);
            }
            if (nr == CHUNK) {
                float* dst = out + (size_t)b * QN_ * CQ_ + (size_t)(q0 + m * 16) * CQ_;
#pragma unroll
                for (int t = 0; t < 2; ++t)
                    wmma::store_matrix_sync(dst + (ng + t) * 16, c[t], CQ_, wmma::mem_row_major);
            } else {
#pragma unroll
                for (int t = 0; t < 2; ++t)
                    wmma::store_matrix_sync(s_ost + m * 16 * CQ_ + (ng + t) * 16, c[t],
                                            CQ_, wmma::mem_row_major);
            }
        }
        if (nr != CHUNK) {
            __syncthreads();
            float4* ob = (float4*)(out + (size_t)b * QN_ * CQ_ + (size_t)q0 * CQ_);
            for (int i = tid; i < nr * 48; i += NT) ob[i] = ((float4*)s_ost)[i];
        }
        __syncthreads();
    }
}

extern "C" void kernel_launch(void* const* d_in, const int* in_sizes, int n_in,
                              void* d_out, int out_size) {
    const float* kv         = (const float*)d_in[0];
    const float* q          = (const float*)d_in[1];
    const float* w_kv       = (const float*)d_in[2];
    const float* b_kv       = (const float*)d_in[3];
    const float* w_q        = (const float*)d_in[4];
    const float* b_q        = (const float*)d_in[5];
    const float* bias_table = (const float*)d_in[6];
    const float* w_proj     = (const float*)d_in[7];
    const float* b_proj     = (const float*)d_in[8];
    float* out = (float*)d_out;

    const int B = in_sizes[0] / (NKEY * DIM_);              // 2048
    const int nfrag = NF_KV + NF_Q + NF_P;                  // 1812
    pack_frags<<<(nfrag + 7) / 8, 256>>>(w_kv, b_kv, w_q, b_q, w_proj, b_proj);
    pack_bias<<<(NH_ * 49 * NKEY + 511) / 512, 512>>>(bias_table);

    cudaFuncSetAttribute(wca_kernel, cudaFuncAttributeMaxDynamicSharedMemorySize, SMEM_BYTES);
    wca_kernel<<<B, NT, SMEM_BYTES>>>(kv, q, out);
}

// round 8
// speedup vs baseline: 13.3086x; 1.1623x over previous
#include <cuda_runtime.h>
#include <cuda_fp16.h>
#include <mma.h>
#include <cstdint>

using namespace nvcuda;

namespace {
constexpr int NKEY = 49;
constexpr int QN_  = 196;
constexpr int DIM_ = 384;
constexpr int NH_  = 12;
constexpr int HD_  = 32;
constexpr int CQ_  = 192;
constexpr float SCALE_ = 0.17677669529663687f;

constexpr int NT    = 384;   // 12 warps
constexpr int NW    = 12;
constexpr int CHUNK = 64;    // q rows per chunk (dynamic m-tile count)
constexpr int NKP   = 64;    // padded keys / kv rows

constexpr int SKVH = 392;    // K/V row stride (halves)
constexpr int SQP  = 392;    // qp / x row stride (halves)
constexpr int SQIN = 200;    // q-input row stride (halves)
constexpr int STGF = 68;     // attention staging stride (f32)

// smem byte offsets
constexpr int OFF_K   = 0;                            // 64*392*2 = 50176
constexpr int OFF_V   = 50176;
constexpr int OFF_SCR = 100352;                       // qin 64x200 half / ost 16x192 f32
constexpr int OFF_QP  = OFF_SCR + 25600;              // 125952: qp 64x392 half / s_x phase1
constexpr int OFF_STG = OFF_QP + 50176;               // 176128: 12 * 16*68*4 = 52224
constexpr int OFF_QC  = OFF_STG + NW * 16 * STGF * 4; // 228352
constexpr int OFF_ONE = OFF_QC + CHUNK * 4;           // 228608
constexpr int SMEM_BYTES = OFF_ONE + 512;             // 229120

using FragA  = wmma::fragment<wmma::matrix_a, 16, 16, 16, __half, wmma::row_major>;
using FragBR = wmma::fragment<wmma::matrix_b, 16, 16, 16, __half, wmma::row_major>;
using FragBC = wmma::fragment<wmma::matrix_b, 16, 16, 16, __half, wmma::col_major>;
using FragC  = wmma::fragment<wmma::accumulator, 16, 16, 16, float>;
using FragCH = wmma::fragment<wmma::accumulator, 16, 16, 16, __half>;

constexpr int NF_KV = 25 * 48;   // 24 k-steps + bias, 48 n-tiles
constexpr int NF_Q  = 13 * 24;   // 12 + bias, 24 n-tiles
constexpr int NF_P  = 25 * 12;   // 24 + bias, 12 n-tiles
}

__device__ uint4 g_wkv_f[NF_KV * 32];
__device__ uint4 g_wq_f [NF_Q  * 32];
__device__ uint4 g_wp_f [NF_P  * 32];
__device__ float g_bias_f[NH_ * 49 * NKEY];

__device__ __forceinline__ void expand_b(FragBR& f, uint4 v) {
    unsigned int w[4] = {v.x, v.y, v.z, v.w};
#pragma unroll
    for (int i = 0; i < 4; ++i) {
        const __half2 h2 = *reinterpret_cast<const __half2*>(&w[i]);
        f.x[2 * i]     = __low2half(h2);
        f.x[2 * i + 1] = __high2half(h2);
    }
}

__device__ __forceinline__ void cvt_store_half(__half* dst, int ld, const FragC& c) {
    FragCH h;
#pragma unroll
    for (int i = 0; i < 8; ++i) h.x[i] = __float2half_rn(c.x[i]);
    wmma::store_matrix_sync(dst, h, ld, wmma::mem_row_major);
}

// ---------------- setup kernels ----------------
__global__ void pack_frags(const float* __restrict__ w_kv, const float* __restrict__ b_kv,
                           const float* __restrict__ w_q,  const float* __restrict__ b_q,
                           const float* __restrict__ w_proj, const float* __restrict__ b_proj) {
    __shared__ __half tiles[8][256];
    const int w    = blockIdx.x * 8 + (threadIdx.x >> 5);
    const int lane = threadIdx.x & 31;
    __half* tile = tiles[threadIdx.x >> 5];
    uint4* dst;
    if (w < NF_KV) {
        const int ks = w / 48, nt = w - ks * 48, n0 = nt * 16;
        for (int e = lane; e < 256; e += 32) {
            const int r = e >> 4, c = e & 15;
            float v;
            if (ks < 24) v = w_kv[(ks * 16 + r) * 768 + n0 + c];
            else         v = (r == 0) ? b_kv[n0 + c] : 0.0f;
            tile[e] = __float2half_rn(v);
        }
        dst = g_wkv_f + w * 32;
    } else if (w < NF_KV + NF_Q) {
        const int w2 = w - NF_KV, ks = w2 / 24, nt = w2 - ks * 24, n0 = nt * 16;
        for (int e = lane; e < 256; e += 32) {
            const int r = e >> 4, c = e & 15;
            float v;
            if (ks < 12) v = w_q[(ks * 16 + r) * DIM_ + n0 + c] * SCALE_;
            else         v = (r == 0) ? b_q[n0 + c] * SCALE_ : 0.0f;
            tile[e] = __float2half_rn(v);
        }
        dst = g_wq_f + w2 * 32;
    } else if (w < NF_KV + NF_Q + NF_P) {
        const int w3 = w - NF_KV - NF_Q, ks = w3 / 12, nt = w3 - ks * 12, n0 = nt * 16;
        for (int e = lane; e < 256; e += 32) {
            const int r = e >> 4, c = e & 15;
            float v;
            if (ks < 24) v = w_proj[(ks * 16 + r) * CQ_ + n0 + c];
            else         v = (r == 0) ? b_proj[n0 + c] : 0.0f;
            tile[e] = __float2half_rn(v);
        }
        dst = g_wp_f + w3 * 32;
    } else return;
    __syncwarp();
    FragBR f;
    wmma::load_matrix_sync(f, tile, 16);
    unsigned int w4[4];
#pragma unroll
    for (int i = 0; i < 4; ++i) {
        __half2 h2 = __halves2half2(f.x[2 * i], f.x[2 * i + 1]);
        w4[i] = *reinterpret_cast<unsigned int*>(&h2);
    }
    dst[lane] = make_uint4(w4[0], w4[1], w4[2], w4[3]);
}

__global__ void pack_bias(const float* __restrict__ bias_table) {
    const int idx = blockIdx.x * blockDim.x + threadIdx.x;
    if (idx >= NH_ * 49 * NKEY) return;
    const int h   = idx / (49 * NKEY);
    const int rem = idx - h * 49 * NKEY;
    const int qc  = rem / NKEY;
    const int key = rem - qc * NKEY;
    const int qi2 = qc / 7, qj2 = qc - qi2 * 7;
    const int kp  = key * 4;
    const int ki  = kp / 14, kj = kp - ki * 14;
    const int dh  = qi2 - (ki >> 1) + 6;
    const int dw  = qj2 - (kj >> 1) + 6;
    g_bias_f[idx] = bias_table[(dh * 13 + dw) * NH_ + h];
}

// ---------------- main kernel ----------------
__global__ __launch_bounds__(NT, 1)
void wca_kernel(const float* __restrict__ kv, const float* __restrict__ q,
                float* __restrict__ out)
{
    extern __shared__ char smb[];
    __half* s_k   = (__half*)(smb + OFF_K);
    __half* s_v   = (__half*)(smb + OFF_V);
    __half* s_qin = (__half*)(smb + OFF_SCR);   // chunk: 64x200 half
    float*  s_ost = (float*)(smb + OFF_SCR);    // partial chunk: 16x192 f32
    __half* s_qp  = (__half*)(smb + OFF_QP);    // 64x392 half (phase1: s_x)
    __half* s_x   = (__half*)(smb + OFF_QP);
    float*  s_stg = (float*)(smb + OFF_STG);    // 12 x (16 x 68) f32
    int*    s_qc  = (int*)(smb + OFF_QC);
    __half* s_one = (__half*)(smb + OFF_ONE);   // 16x16 ones-column tile

    const int b    = blockIdx.x;
    const int tid  = threadIdx.x;
    const int wid  = tid >> 5;
    const int lane = tid & 31;
    float* wstg = s_stg + wid * (16 * STGF);

    // ---- phase 0: X load (49 rows) + zero pad rows, ones tile ----
    {
        const float4* src = (const float4*)(kv + (size_t)b * NKEY * DIM_);
        for (int i = tid; i < NKEY * 96; i += NT) {
            const int r = i / 96, c4 = (i - r * 96) * 4;
            const float4 v = src[i];
            __half* d = s_x + r * SQP + c4;
            d[0] = __float2half_rn(v.x); d[1] = __float2half_rn(v.y);
            d[2] = __float2half_rn(v.z); d[3] = __float2half_rn(v.w);
        }
        for (int i = tid; i < (NKP - NKEY) * SQP; i += NT)
            s_x[NKEY * SQP + i] = __float2half_rn(0.0f);
        if (tid < 256) s_one[tid] = __float2half_rn((tid & 15) == 0 ? 1.0f : 0.0f);
    }
    __syncthreads();

    // ---- phase 1: kv projection, B-stationary over all 4 m-tiles ----
    {
        FragA ones;
        wmma::load_matrix_sync(ones, s_one, 16);
        for (int j = 0; j < 2; ++j) {
            const int nt0 = (wid * 2 + j) * 2;       // 2 n-tiles per job
            FragC c[4][2];
#pragma unroll
            for (int m = 0; m < 4; ++m) {
                wmma::fill_fragment(c[m][0], 0.0f);
                wmma::fill_fragment(c[m][1], 0.0f);
            }
            uint4 nb0 = g_wkv_f[(0 * 48 + nt0) * 32 + lane];
            uint4 nb1 = g_wkv_f[(0 * 48 + nt0 + 1) * 32 + lane];
            for (int ks = 0; ks < 24; ++ks) {
                FragBR b0, b1;
                expand_b(b0, nb0);
                expand_b(b1, nb1);
                nb0 = g_wkv_f[((ks + 1) * 48 + nt0) * 32 + lane];       // ks=23 -> bias frags
                nb1 = g_wkv_f[((ks + 1) * 48 + nt0 + 1) * 32 + lane];
#pragma unroll
                for (int m = 0; m < 4; ++m) {
                    FragA a;
                    wmma::load_matrix_sync(a, s_x + m * 16 * SQP + ks * 16, SQP);
                    wmma::mma_sync(c[m][0], a, b0, c[m][0]);
                    wmma::mma_sync(c[m][1], a, b1, c[m][1]);
                }
            }
            {   // bias k-step
                FragBR b0, b1;
                expand_b(b0, nb0);
                expand_b(b1, nb1);
#pragma unroll
                for (int m = 0; m < 4; ++m) {
                    wmma::mma_sync(c[m][0], ones, b0, c[m][0]);
                    wmma::mma_sync(c[m][1], ones, b1, c[m][1]);
                }
            }
#pragma unroll
            for (int t = 0; t < 2; ++t) {
                const int colg = (nt0 + t) * 16;
                __half* dst = (colg < DIM_) ? (s_k + colg) : (s_v + colg - DIM_);
#pragma unroll
                for (int m = 0; m < 4; ++m)
                    cvt_store_half(dst + m * 16 * SKVH, SKVH, c[m][t]);
            }
        }
    }
    __syncthreads();

    // ---- phase 2: q chunks of up to 64 rows ----
    for (int q0 = 0; q0 < QN_; q0 += CHUNK) {
        const int nr = min(CHUNK, QN_ - q0);
        const int mt = (nr + 15) >> 4;               // m-tiles this chunk

        // 2a: q chunk -> half (zero pad to mt*16 rows), q-cells
        {
            const float4* src = (const float4*)(q + (size_t)b * QN_ * CQ_ + (size_t)q0 * CQ_);
            for (int i = tid; i < mt * 16 * 48; i += NT) {
                const int r = i / 48, c4 = (i - r * 48) * 4;
                float4 v = make_float4(0.f, 0.f, 0.f, 0.f);
                if (r < nr) v = src[i];
                __half* d = s_qin + r * SQIN + c4;
                d[0] = __float2half_rn(v.x); d[1] = __float2half_rn(v.y);
                d[2] = __float2half_rn(v.z); d[3] = __float2half_rn(v.w);
            }
            if (tid < mt * 16) {
                const int qr = min(q0 + tid, QN_ - 1);
                const int qi = qr / 14, qj = qr - qi * 14;
                s_qc[tid] = (qi >> 1) * 7 + (qj >> 1);
            }
        }
        __syncthreads();

        // 2b: q projection — warp = 2 n-tiles x mt m-tiles
        {
            FragA ones;
            wmma::load_matrix_sync(ones, s_one, 16);
            const int nt0 = wid * 2;
            FragC c[4][2];
            for (int m = 0; m < mt; ++m) {
                wmma::fill_fragment(c[m][0], 0.0f);
                wmma::fill_fragment(c[m][1], 0.0f);
            }
            uint4 nb0 = g_wq_f[(0 * 24 + nt0) * 32 + lane];
            uint4 nb1 = g_wq_f[(0 * 24 + nt0 + 1) * 32 + lane];
            for (int ks = 0; ks < 12; ++ks) {
                FragBR b0, b1;
                expand_b(b0, nb0);
                expand_b(b1, nb1);
                nb0 = g_wq_f[((ks + 1) * 24 + nt0) * 32 + lane];
                nb1 = g_wq_f[((ks + 1) * 24 + nt0 + 1) * 32 + lane];
                for (int m = 0; m < mt; ++m) {
                    FragA a;
                    wmma::load_matrix_sync(a, s_qin + m * 16 * SQIN + ks * 16, SQIN);
                    wmma::mma_sync(c[m][0], a, b0, c[m][0]);
                    wmma::mma_sync(c[m][1], a, b1, c[m][1]);
                }
            }
            {
                FragBR b0, b1;
                expand_b(b0, nb0);
                expand_b(b1, nb1);
                for (int m = 0; m < mt; ++m) {
                    wmma::mma_sync(c[m][0], ones, b0, c[m][0]);
                    wmma::mma_sync(c[m][1], ones, b1, c[m][1]);
                }
            }
            for (int m = 0; m < mt; ++m) {
                cvt_store_half(s_qp + m * 16 * SQP + nt0 * 16, SQP, c[m][0]);
                cvt_store_half(s_qp + m * 16 * SQP + (nt0 + 1) * 16, SQP, c[m][1]);
            }
        }
        __syncthreads();

        // 2c: attention — warp = head; mt sub-chunks of 16 rows
        {
            const int h = wid;
            const int base = h * HD_;
            for (int s = 0; s < mt; ++s) {
                const int r0 = s * 16;
                FragC sf[4];
#pragma unroll
                for (int t = 0; t < 4; ++t) wmma::fill_fragment(sf[t], 0.0f);
#pragma unroll
                for (int ks = 0; ks < 2; ++ks) {
                    FragA a;
                    wmma::load_matrix_sync(a, s_qp + r0 * SQP + base + ks * 16, SQP);
#pragma unroll
                    for (int t = 0; t < 4; ++t) {
                        FragBC bk;
                        wmma::load_matrix_sync(bk, s_k + (t * 16) * SKVH + base + ks * 16, SKVH);
                        wmma::mma_sync(sf[t], a, bk, sf[t]);
                    }
                }
#pragma unroll
                for (int t = 0; t < 4; ++t)
                    wmma::store_matrix_sync(wstg + t * 16, sf[t], STGF, wmma::mem_row_major);
                __syncwarp();

                // softmax: 2 lanes per row; pre-normalized half P over 64 keys
                {
                    const int r = lane >> 1, par = lane & 1;
                    float* row = wstg + r * STGF;
                    const float* brow = g_bias_f + (h * 49 + s_qc[r0 + r]) * NKEY;
                    float vals[25];
                    int cnt = 0;
                    float mx = -1e30f;
                    for (int c = par; c < NKEY; c += 2) {
                        const float v = row[c] + brow[c];
                        vals[cnt++] = v;
                        mx = fmaxf(mx, v);
                    }
                    mx = fmaxf(mx, __shfl_xor_sync(0xffffffffu, mx, 1));
                    float ssum = 0.f;
                    for (int i = 0; i < cnt; ++i) {
                        const float p = __expf(vals[i] - mx);
                        vals[i] = p;
                        ssum += p;
                    }
                    ssum += __shfl_xor_sync(0xffffffffu, ssum, 1);
                    const float inv = 1.0f / ssum;
                    __half* prow = (__half*)wstg + r * (STGF * 2);
                    int i = 0;
                    for (int c = par; c < 64; c += 2) {
                        const float p = (c < NKEY) ? vals[i++] * inv : 0.0f;
                        prow[c] = __float2half_rn(p);
                    }
                }
                __syncwarp();

                // O = Pn V over 64 keys
                FragC o[2];
                wmma::fill_fragment(o[0], 0.0f);
                wmma::fill_fragment(o[1], 0.0f);
#pragma unroll
                for (int ks = 0; ks < 4; ++ks) {
                    FragA a;
                    wmma::load_matrix_sync(a, (__half*)wstg + ks * 16, STGF * 2);
#pragma unroll
                    for (int t = 0; t < 2; ++t) {
                        FragBR bv;
                        wmma::load_matrix_sync(bv, s_v + ks * 16 * SKVH + base + t * 16, SKVH);
                        wmma::mma_sync(o[t], a, bv, o[t]);
                    }
                }
#pragma unroll
                for (int t = 0; t < 2; ++t)
                    cvt_store_half(s_qp + r0 * SQP + base + t * 16, SQP, o[t]);
                __syncwarp();
            }
        }
        __syncthreads();

        // 2d: out projection — warp = 1 n-tile x mt m-tiles
        {
            FragA ones;
            wmma::load_matrix_sync(ones, s_one, 16);
            const int nt = wid;
            FragC c[4];
            for (int m = 0; m < mt; ++m) wmma::fill_fragment(c[m], 0.0f);
            uint4 nb = g_wp_f[(0 * 12 + nt) * 32 + lane];
            for (int ks = 0; ks < 24; ++ks) {
                FragBR bw;
                expand_b(bw, nb);
                nb = g_wp_f[((ks + 1) * 12 + nt) * 32 + lane];
                for (int m = 0; m < mt; ++m) {
                    FragA a;
                    wmma::load_matrix_sync(a, s_qp + m * 16 * SQP + ks * 16, SQP);
                    wmma::mma_sync(c[m], a, bw, c[m]);
                }
            }
            {
                FragBR bw;
                expand_b(bw, nb);
                for (int m = 0; m < mt; ++m) wmma::mma_sync(c[m], ones, bw, c[m]);
            }
            if (nr == CHUNK) {
                float* dst = out + (size_t)b * QN_ * CQ_ + (size_t)q0 * CQ_ + nt * 16;
                for (int m = 0; m < mt; ++m)
                    wmma::store_matrix_sync(dst + m * 16 * CQ_, c[m], CQ_, wmma::mem_row_major);
            } else {
                for (int m = 0; m < mt; ++m)
                    wmma::store_matrix_sync(s_ost + m * 16 * CQ_ + nt * 16, c[m],
                                            CQ_, wmma::mem_row_major);
            }
        }
        if (nr != CHUNK) {
            __syncthreads();
            float4* ob = (float4*)(out + (size_t)b * QN_ * CQ_ + (size_t)q0 * CQ_);
            for (int i = tid; i < nr * 48; i += NT) ob[i] = ((float4*)s_ost)[i];
        }
        __syncthreads();
    }
}

extern "C" void kernel_launch(void* const* d_in, const int* in_sizes, int n_in,
                              void* d_out, int out_size) {
    const float* kv         = (const float*)d_in[0];
    const float* q          = (const float*)d_in[1];
    const float* w_kv       = (const float*)d_in[2];
    const float* b_kv       = (const float*)d_in[3];
    const float* w_q        = (const float*)d_in[4];
    const float* b_q        = (const float*)d_in[5];
    const float* bias_table = (const float*)d_in[6];
    const float* w_proj     = (const float*)d_in[7];
    const float* b_proj     = (const float*)d_in[8];
    float* out = (float*)d_out;

    const int B = in_sizes[0] / (NKEY * DIM_);              // 2048
    const int nfrag = NF_KV + NF_Q + NF_P;                  // 1812
    pack_frags<<<(nfrag + 7) / 8, 256>>>(w_kv, b_kv, w_q, b_q, w_proj, b_proj);
    pack_bias<<<(NH_ * 49 * NKEY + 511) / 512, 512>>>(bias_table);

    cudaFuncSetAttribute(wca_kernel, cudaFuncAttributeMaxDynamicSharedMemorySize, SMEM_BYTES);
    wca_kernel<<<B, NT, SMEM_BYTES>>>(kv, q, out);
}